// round 10
// baseline (speedup 1.0000x reference)
#include <cuda_runtime.h>
#include <math.h>

// ---------------- problem constants ----------------
#define BATCH 32
#define DM    512
#define DFF   2048
#define LE    512      // encoder length
#define LDEC  592      // decoder length (label 256 + pred 336)
#define CC    7
#define MMK   4
#define LABEL 256
#define PRED  336
#define KSZ   25
#define KHALF 12
#define NCH   8        // time chunks for sliding-window decomp

// ---------------- device scratch (static, no allocation) ----------------
__device__ float g_x   [BATCH*LDEC*DM];
__device__ float g_sum [BATCH*LDEC*DM];
__device__ float g_q   [BATCH*LDEC*DM];
__device__ float g_k   [BATCH*LDEC*DM];
__device__ float g_v   [BATCH*LDEC*DM];
__device__ float g_agg [BATCH*LDEC*DM];
__device__ float g_enc [BATCH*LE*DM];
__device__ float g_ffn [BATCH*LDEC*DFF];
__device__ float g_tsum[BATCH*LDEC*DM];
__device__ float g_mc  [BATCH*LDEC];
__device__ float g_wts [BATCH*32];
__device__ int   g_dly [BATCH*32];
__device__ float g_cm  [BATCH*DM];
__device__ float g_m7  [BATCH*CC];
__device__ float g_s7  [BATCH*LE*CC];
__device__ float g_t7  [BATCH*LE*CC];
__device__ float g_sdec[BATCH*LDEC*CC];
__device__ float g_tdec[BATCH*LDEC*CC];
__device__ float g_mdec[BATCH*LDEC*MMK];

// ---------------- fp32 GEMM: C = A(MxK) @ B(KxN) (+bias)(+res)(+gelu) ----------------
// 128x128 tile, BK=16, 256 threads, 8x8 micro-tile (split 4+4 at +-64 for
// conflict-free LDS.128), double-buffered smem, float4 global loads/stores.
// REQUIRES: M % 128 == 0, N % 128 == 0, K % 16 == 0.
// res (optional): residual added in epilogue (indexed like C). Never combined with gelu.
// rpbIn/rpbOut remap output row index (write 512-row projections into a
// 592-row-per-batch padded layout for cross attention).
__global__ void __launch_bounds__(256) gemm_nn(
    const float* __restrict__ A, const float* __restrict__ B,
    const float* __restrict__ bias, const float* __restrict__ res,
    float* __restrict__ C,
    int M, int N, int K, int rpbIn, int rpbOut, int gelu)
{
    __shared__ float As[2][16][132];
    __shared__ float Bs[2][16][132];
    int tid = threadIdx.x;
    int tx = tid & 15, ty = tid >> 4;
    int m0 = blockIdx.y * 128, n0 = blockIdx.x * 128;

    int arow = tid >> 2;            // 0..63  (second row = +64)
    int acol = (tid & 3) * 4;       // k quad
    int brow = tid >> 5;            // 0..7   (second row = +8)
    int bcol = (tid & 31) * 4;      // n quad
    const float* Ap0 = A + (size_t)(m0 + arow) * K + acol;
    const float* Ap1 = Ap0 + (size_t)64 * K;
    const float* Bp0 = B + (size_t)brow * N + n0 + bcol;
    const float* Bp1 = Bp0 + (size_t)8 * N;

    float4 a0v, a1v, b0v, b1v;
    float acc[8][8];
#pragma unroll
    for (int i = 0; i < 8; i++)
#pragma unroll
        for (int j = 0; j < 8; j++) acc[i][j] = 0.f;

    // prologue fetch of tile 0
    a0v = *(const float4*)(Ap0);
    a1v = *(const float4*)(Ap1);
    b0v = *(const float4*)(Bp0);
    b1v = *(const float4*)(Bp1);
    {
        As[0][acol + 0][arow] = a0v.x; As[0][acol + 1][arow] = a0v.y;
        As[0][acol + 2][arow] = a0v.z; As[0][acol + 3][arow] = a0v.w;
        As[0][acol + 0][arow + 64] = a1v.x; As[0][acol + 1][arow + 64] = a1v.y;
        As[0][acol + 2][arow + 64] = a1v.z; As[0][acol + 3][arow + 64] = a1v.w;
        *(float4*)&Bs[0][brow][bcol]     = b0v;
        *(float4*)&Bs[0][brow + 8][bcol] = b1v;
    }
    __syncthreads();

    int buf = 0;
    for (int k0 = 0; k0 < K; k0 += 16) {
        bool more = (k0 + 16 < K);
        if (more) {
            a0v = *(const float4*)(Ap0 + k0 + 16);
            a1v = *(const float4*)(Ap1 + k0 + 16);
            b0v = *(const float4*)(Bp0 + (size_t)(k0 + 16) * N);
            b1v = *(const float4*)(Bp1 + (size_t)(k0 + 16) * N);
        }
#pragma unroll
        for (int k = 0; k < 16; k++) {
            float4 x0 = *(const float4*)&As[buf][k][ty * 4];
            float4 x1 = *(const float4*)&As[buf][k][64 + ty * 4];
            float4 y0 = *(const float4*)&Bs[buf][k][tx * 4];
            float4 y1 = *(const float4*)&Bs[buf][k][64 + tx * 4];
            float av[8] = {x0.x, x0.y, x0.z, x0.w, x1.x, x1.y, x1.z, x1.w};
            float bv[8] = {y0.x, y0.y, y0.z, y0.w, y1.x, y1.y, y1.z, y1.w};
#pragma unroll
            for (int i = 0; i < 8; i++)
#pragma unroll
                for (int j = 0; j < 8; j++) acc[i][j] += av[i] * bv[j];
        }
        if (more) {
            int nb = buf ^ 1;
            As[nb][acol + 0][arow] = a0v.x; As[nb][acol + 1][arow] = a0v.y;
            As[nb][acol + 2][arow] = a0v.z; As[nb][acol + 3][arow] = a0v.w;
            As[nb][acol + 0][arow + 64] = a1v.x; As[nb][acol + 1][arow + 64] = a1v.y;
            As[nb][acol + 2][arow + 64] = a1v.z; As[nb][acol + 3][arow + 64] = a1v.w;
            *(float4*)&Bs[nb][brow][bcol]     = b0v;
            *(float4*)&Bs[nb][brow + 8][bcol] = b1v;
            __syncthreads();
            buf = nb;
        }
    }

    // epilogue: bias / residual / gelu / float4 stores
    float4 bia0 = make_float4(0.f, 0.f, 0.f, 0.f), bia1 = bia0;
    if (bias) {
        bia0 = *(const float4*)&bias[n0 + tx * 4];
        bia1 = *(const float4*)&bias[n0 + 64 + tx * 4];
    }
#pragma unroll
    for (int ri = 0; ri < 8; ri++) {
        int gm = m0 + ((ri >> 2) * 64) + ty * 4 + (ri & 3);
        int orow = gm;
        if (rpbIn != rpbOut) orow = (gm / rpbIn) * rpbOut + (gm % rpbIn);
        float4 c0 = make_float4(acc[ri][0] + bia0.x, acc[ri][1] + bia0.y,
                                acc[ri][2] + bia0.z, acc[ri][3] + bia0.w);
        float4 c1 = make_float4(acc[ri][4] + bia1.x, acc[ri][5] + bia1.y,
                                acc[ri][6] + bia1.z, acc[ri][7] + bia1.w);
        if (res) {
            float4 r0 = *(const float4*)&res[(size_t)orow * N + n0 + tx * 4];
            float4 r1 = *(const float4*)&res[(size_t)orow * N + n0 + 64 + tx * 4];
            c0.x += r0.x; c0.y += r0.y; c0.z += r0.z; c0.w += r0.w;
            c1.x += r1.x; c1.y += r1.y; c1.z += r1.z; c1.w += r1.w;
        }
        if (gelu) {
            c0.x *= normcdff(c0.x); c0.y *= normcdff(c0.y);
            c0.z *= normcdff(c0.z); c0.w *= normcdff(c0.w);
            c1.x *= normcdff(c1.x); c1.y *= normcdff(c1.y);
            c1.z *= normcdff(c1.z); c1.w *= normcdff(c1.w);
        }
        *(float4*)&C[(size_t)orow * N + n0 + tx * 4]      = c0;
        *(float4*)&C[(size_t)orow * N + n0 + 64 + tx * 4] = c1;
    }
}

// ---------------- batched NT GEMM + diagonal fold ----------------
// Computes S[b,i,j] = sum_d Q[b,i,d]*K[b,j,d] tile-locally, then folds
// mc[b,tau] += (1/DM) * sum_{(i-j) mod L == tau} S[i,j] WITHOUT materializing S.
// Lk = number of valid K rows (< L when K is zero-padded); column tiles fully
// beyond Lk are skipped via grid sizing, partial tile handled by bok guards.
// Fast fold path: per thread, the 64 (ri,ci) products hit only 21 distinct
// tau bins (64*d1 + 4*(ty-tx) + d2); pre-reduce in registers, then 21 atomics.
// mc must be pre-zeroed.
__global__ void __launch_bounds__(256) gemm_nt_fold(
    const float* __restrict__ Q, const float* __restrict__ Km,
    float* __restrict__ mc, int L, int Lk, int D)
{
    __shared__ float As[2][16][132];
    __shared__ float Bs[2][16][132];
    __shared__ float bins[255];
    int b = blockIdx.z;
    const float* Ab = Q  + (size_t)b * L * D;
    const float* Bb = Km + (size_t)b * L * D;
    int tid = threadIdx.x;
    int tx = tid & 15, ty = tid >> 4;
    int m0 = blockIdx.y * 128, n0 = blockIdx.x * 128;

    int row = tid >> 2;            // 0..63 (+64)
    int col4 = (tid & 3) * 4;      // d quad
    bool aok0 = (m0 + row)      < L;
    bool aok1 = (m0 + row + 64) < L;
    bool bok0 = (n0 + row)      < Lk;
    bool bok1 = (n0 + row + 64) < Lk;
    const float* Ap0 = Ab + (size_t)(m0 + row) * D + col4;
    const float* Ap1 = Ap0 + (size_t)64 * D;
    const float* Bp0 = Bb + (size_t)(n0 + row) * D + col4;
    const float* Bp1 = Bp0 + (size_t)64 * D;

    float4 zf = make_float4(0.f, 0.f, 0.f, 0.f);
    float4 a0v, a1v, b0v, b1v;
    float acc[8][8];
#pragma unroll
    for (int i = 0; i < 8; i++)
#pragma unroll
        for (int j = 0; j < 8; j++) acc[i][j] = 0.f;

    a0v = aok0 ? *(const float4*)(Ap0) : zf;
    a1v = aok1 ? *(const float4*)(Ap1) : zf;
    b0v = bok0 ? *(const float4*)(Bp0) : zf;
    b1v = bok1 ? *(const float4*)(Bp1) : zf;
    {
        As[0][col4 + 0][row] = a0v.x; As[0][col4 + 1][row] = a0v.y;
        As[0][col4 + 2][row] = a0v.z; As[0][col4 + 3][row] = a0v.w;
        As[0][col4 + 0][row + 64] = a1v.x; As[0][col4 + 1][row + 64] = a1v.y;
        As[0][col4 + 2][row + 64] = a1v.z; As[0][col4 + 3][row + 64] = a1v.w;
        Bs[0][col4 + 0][row] = b0v.x; Bs[0][col4 + 1][row] = b0v.y;
        Bs[0][col4 + 2][row] = b0v.z; Bs[0][col4 + 3][row] = b0v.w;
        Bs[0][col4 + 0][row + 64] = b1v.x; Bs[0][col4 + 1][row + 64] = b1v.y;
        Bs[0][col4 + 2][row + 64] = b1v.z; Bs[0][col4 + 3][row + 64] = b1v.w;
    }
    __syncthreads();

    int buf = 0;
    for (int k0 = 0; k0 < D; k0 += 16) {
        bool more = (k0 + 16 < D);
        if (more) {
            a0v = aok0 ? *(const float4*)(Ap0 + k0 + 16) : zf;
            a1v = aok1 ? *(const float4*)(Ap1 + k0 + 16) : zf;
            b0v = bok0 ? *(const float4*)(Bp0 + k0 + 16) : zf;
            b1v = bok1 ? *(const float4*)(Bp1 + k0 + 16) : zf;
        }
#pragma unroll
        for (int k = 0; k < 16; k++) {
            float4 x0 = *(const float4*)&As[buf][k][ty * 4];
            float4 x1 = *(const float4*)&As[buf][k][64 + ty * 4];
            float4 y0 = *(const float4*)&Bs[buf][k][tx * 4];
            float4 y1 = *(const float4*)&Bs[buf][k][64 + tx * 4];
            float av[8] = {x0.x, x0.y, x0.z, x0.w, x1.x, x1.y, x1.z, x1.w};
            float bv[8] = {y0.x, y0.y, y0.z, y0.w, y1.x, y1.y, y1.z, y1.w};
#pragma unroll
            for (int i = 0; i < 8; i++)
#pragma unroll
                for (int j = 0; j < 8; j++) acc[i][j] += av[i] * bv[j];
        }
        if (more) {
            int nb = buf ^ 1;
            As[nb][col4 + 0][row] = a0v.x; As[nb][col4 + 1][row] = a0v.y;
            As[nb][col4 + 2][row] = a0v.z; As[nb][col4 + 3][row] = a0v.w;
            As[nb][col4 + 0][row + 64] = a1v.x; As[nb][col4 + 1][row + 64] = a1v.y;
            As[nb][col4 + 2][row + 64] = a1v.z; As[nb][col4 + 3][row + 64] = a1v.w;
            Bs[nb][col4 + 0][row] = b0v.x; Bs[nb][col4 + 1][row] = b0v.y;
            Bs[nb][col4 + 2][row] = b0v.z; Bs[nb][col4 + 3][row] = b0v.w;
            Bs[nb][col4 + 0][row + 64] = b1v.x; Bs[nb][col4 + 1][row + 64] = b1v.y;
            Bs[nb][col4 + 2][row + 64] = b1v.z; Bs[nb][col4 + 3][row + 64] = b1v.w;
            __syncthreads();
            buf = nb;
        }
    }

    // ---- fold into per-CTA tau bins ----
    __syncthreads();
    for (int i = tid; i < 255; i += 256) bins[i] = 0.f;
    __syncthreads();

    bool fullTile = (m0 + 128 <= L) && (n0 + 128 <= Lk);
    if (fullTile) {
        // register pre-reduction: tau_local = 64*d1 + 4*(ty-tx) + d2 + 127,
        // d1 = (ri>>2)-(ci>>2) in [-1,1], d2 = (ri&3)-(ci&3) in [-3,3]
        float tb[3][7];
#pragma unroll
        for (int i = 0; i < 3; i++)
#pragma unroll
            for (int j = 0; j < 7; j++) tb[i][j] = 0.f;
#pragma unroll
        for (int ri = 0; ri < 8; ri++)
#pragma unroll
            for (int ci = 0; ci < 8; ci++)
                tb[(ri >> 2) - (ci >> 2) + 1][(ri & 3) - (ci & 3) + 3] += acc[ri][ci];
        int baseOff = (ty - tx) * 4 + 127;
#pragma unroll
        for (int i = 0; i < 3; i++)
#pragma unroll
            for (int j = 0; j < 7; j++)
                atomicAdd(&bins[baseOff + 64 * (i - 1) + (j - 3)], tb[i][j]);
    } else {
#pragma unroll
        for (int ri = 0; ri < 8; ri++) {
            int lm = ((ri >> 2) * 64) + ty * 4 + (ri & 3);
            if (m0 + lm >= L) continue;
#pragma unroll
            for (int ci = 0; ci < 8; ci++) {
                int ln = ((ci >> 2) * 64) + tx * 4 + (ci & 3);
                if (n0 + ln < Lk) atomicAdd(&bins[lm - ln + 127], acc[ri][ci]);
            }
        }
    }
    __syncthreads();
    int base = m0 - n0;
    for (int i = tid; i < 255; i += 256) {
        float vbin = bins[i];
        if (vbin != 0.f) {
            int tau = base + i - 127;
            tau %= L; if (tau < 0) tau += L;
            atomicAdd(&mc[b * L + tau], vbin * (1.f / DM));
        }
    }
}

// ---------------- small kernels ----------------
// one warp per (b,c): grid-strided partial sums + shfl reduce
__global__ void __launch_bounds__(256) k_mean7(const float* __restrict__ x,
                                               float* __restrict__ m7) {
    int wid = (blockIdx.x * blockDim.x + threadIdx.x) >> 5;
    int lane = threadIdx.x & 31;
    if (wid >= BATCH * CC) return;
    int b = wid / CC, c = wid % CC;
    float s = 0.f;
    for (int i = lane; i < LE; i += 32) s += x[(b * LE + i) * CC + c];
#pragma unroll
    for (int o = 16; o > 0; o >>= 1) s += __shfl_down_sync(0xffffffffu, s, o);
    if (lane == 0) m7[wid] = s / LE;
}

__global__ void k_decomp7(const float* __restrict__ x, float* __restrict__ seas,
                          float* __restrict__ tr) {
    int idx = blockIdx.x * blockDim.x + threadIdx.x;
    if (idx >= BATCH * LE * CC) return;
    int c = idx % CC, t = (idx / CC) % LE, b = idx / (CC * LE);
    float s = 0.f;
#pragma unroll
    for (int u = -KHALF; u <= KHALF; u++) {
        int tt = t + u; tt = tt < 0 ? 0 : (tt >= LE ? LE - 1 : tt);
        s += x[(b * LE + tt) * CC + c];
    }
    float m = s * (1.f / KSZ);
    seas[idx] = x[idx] - m;
    tr[idx] = m;
}

__global__ void k_build_dec(const float* __restrict__ s7, const float* __restrict__ t7,
                            const float* __restrict__ m7, float* __restrict__ sdec,
                            float* __restrict__ tdec) {
    int idx = blockIdx.x * blockDim.x + threadIdx.x;
    if (idx >= BATCH * LDEC * CC) return;
    int c = idx % CC, t = (idx / CC) % LDEC, b = idx / (CC * LDEC);
    if (t < LABEL) {
        int src = (b * LE + (LE - LABEL) + t) * CC + c;
        sdec[idx] = s7[src];
        tdec[idx] = t7[src];
    } else {
        sdec[idx] = 0.f;
        tdec[idx] = m7[b * CC + c];
    }
}

__global__ void k_build_mark(const float* __restrict__ me, const float* __restrict__ md,
                             float* __restrict__ out) {
    int idx = blockIdx.x * blockDim.x + threadIdx.x;
    if (idx >= BATCH * LDEC * MMK) return;
    int m = idx % MMK, t = (idx / MMK) % LDEC, b = idx / (MMK * LDEC);
    out[idx] = (t < LABEL) ? me[(b * LE + (LE - LABEL) + t) * MMK + m]
                           : md[(b * PRED + (t - LABEL)) * MMK + m];
}

// circular conv3 embed + mark matmul, 8 time steps per block, weights in regs.
// REQUIRES L % 8 == 0 (512, 592 both OK).
__global__ void __launch_bounds__(512) k_embed(
    const float* __restrict__ x, const float* __restrict__ mark,
    const float* __restrict__ Wc, const float* __restrict__ Wm,
    float* __restrict__ out, int L) {
    __shared__ float xs[10 * CC];     // rows t0-1 .. t0+8 (circular)
    __shared__ float ms[8 * MMK];
    int blk = blockIdx.x;
    int nch = L >> 3;
    int b = blk / nch, t0 = (blk % nch) << 3;
    int tid = threadIdx.x;
    if (tid < 10 * CC) {
        int r = tid / CC, c = tid % CC;
        int tt = (t0 - 1 + r + L) % L;
        xs[tid] = x[(b * L + tt) * CC + c];
    } else if (tid < 10 * CC + 8 * MMK) {
        int q = tid - 10 * CC;
        int r = q / MMK, m = q % MMK;
        ms[q] = mark[(b * L + t0 + r) * MMK + m];
    }
    __syncthreads();
    int o = tid;
    float wc[3 * CC], wm[MMK];
#pragma unroll
    for (int i = 0; i < 3 * CC; i++) wc[i] = Wc[i * DM + o];
#pragma unroll
    for (int m = 0; m < MMK; m++) wm[m] = Wm[m * DM + o];
#pragma unroll
    for (int r = 0; r < 8; r++) {
        float s = 0.f;
#pragma unroll
        for (int w = 0; w < 3; w++)
#pragma unroll
            for (int c = 0; c < CC; c++)
                s += xs[(r + w) * CC + c] * wc[w * CC + c];
#pragma unroll
        for (int m = 0; m < MMK; m++) s += ms[r * MMK + m] * wm[m];
        out[((size_t)(b * L + t0 + r)) * DM + o] = s;
    }
}

__global__ void k_zero(float* __restrict__ p, int n) {
    int i = blockIdx.x * blockDim.x + threadIdx.x;
    int n4 = n >> 2;
    if (i < n4) {
        ((float4*)p)[i] = make_float4(0.f, 0.f, 0.f, 0.f);
    } else {
        int r = n4 * 4 + (i - n4);
        if (r < n) p[r] = 0.f;
    }
}

// zero only the padding rows [r0, rpb) of each batch in a [BATCH, rpb, DM] buffer
// (DM divisible by 4 -> pure float4 path)
__global__ void k_zero_pad(float* __restrict__ p, int r0, int rpb) {
    int idx = blockIdx.x * blockDim.x + threadIdx.x;
    int nPadRows = rpb - r0;
    if (idx >= BATCH * nPadRows * (DM / 4)) return;
    int d4 = idx % (DM / 4);
    int rest = idx / (DM / 4);
    int r = rest % nPadRows;
    int b = rest / nPadRows;
    *(float4*)&p[((size_t)(b * rpb + r0 + r)) * DM + d4 * 4] =
        make_float4(0.f, 0.f, 0.f, 0.f);
}

// sliding-window series_decomp over D=512 channels.
// mode: 0=seasonal only, 1=also write trend, 2=accumulate trend
__global__ void k_decomp_sw(const float* __restrict__ S, float* __restrict__ seas,
                            float* __restrict__ trend, int L, int mode) {
    int idx = blockIdx.x * blockDim.x + threadIdx.x;
    if (idx >= BATCH * DM * NCH) return;
    int d = idx % DM;
    int rest = idx / DM;
    int ch = rest % NCH;
    int b = rest / NCH;
    int CL = (L + NCH - 1) / NCH;
    int t0 = ch * CL;
    int t1 = t0 + CL < L ? t0 + CL : L;
    if (t0 >= L) return;
    const float* base = S + (size_t)b * L * DM + d;
    float s = 0.f;
#pragma unroll
    for (int u = -KHALF; u <= KHALF; u++) {
        int tt = t0 + u; tt = tt < 0 ? 0 : (tt >= L ? L - 1 : tt);
        s += base[(size_t)tt * DM];
    }
    for (int t = t0; t < t1; t++) {
        float m = s * (1.f / KSZ);
        size_t o = ((size_t)(b * L + t)) * DM + d;
        seas[o] = base[(size_t)t * DM] - m;
        if (mode == 1) trend[o] = m;
        else if (mode == 2) trend[o] += m;
        int rm = t - KHALF; rm = rm < 0 ? 0 : rm;
        int ad = t + KHALF + 1; ad = ad >= L ? L - 1 : ad;
        s += base[(size_t)ad * DM] - base[(size_t)rm * DM];
    }
}

__global__ void __launch_bounds__(256) k_topk(const float* __restrict__ mc,
                                              float* __restrict__ w, int* __restrict__ dly,
                                              int L, int K) {
    __shared__ float vals[LDEC];
    __shared__ float rv[256];
    __shared__ int ri[256];
    __shared__ float selv[32];
    __shared__ int seli[32];
    int b = blockIdx.x, tid = threadIdx.x;
    for (int j = tid; j < L; j += 256) vals[j] = mc[b * L + j];
    __syncthreads();
    for (int it = 0; it < K; it++) {
        float best = -1e30f; int bi = 0;
        for (int j = tid; j < L; j += 256) {
            float v = vals[j];
            if (v > best) { best = v; bi = j; }
        }
        rv[tid] = best; ri[tid] = bi;
        __syncthreads();
        for (int s = 128; s > 0; s >>= 1) {
            if (tid < s) {
                if (rv[tid + s] > rv[tid] ||
                    (rv[tid + s] == rv[tid] && ri[tid + s] < ri[tid])) {
                    rv[tid] = rv[tid + s]; ri[tid] = ri[tid + s];
                }
            }
            __syncthreads();
        }
        if (tid == 0) { selv[it] = rv[0]; seli[it] = ri[0]; vals[ri[0]] = -1e30f; }
        __syncthreads();
    }
    if (tid == 0) {
        float mx = selv[0], ssum = 0.f;
        for (int i = 0; i < K; i++) { float e = expf(selv[i] - mx); selv[i] = e; ssum += e; }
        for (int i = 0; i < K; i++) { w[b * 32 + i] = selv[i] / ssum; dly[b * 32 + i] = seli[i]; }
    }
}

// agg[b,t,d4] = sum_i w[b,i] * v[b,(t+delay_i)%L, d4] ; float4 channels,
// 128 threads cover DM=512; w/dly staged in smem.
__global__ void __launch_bounds__(128) k_agg(
    const float* __restrict__ v, const float* __restrict__ w,
    const int* __restrict__ dly, float* __restrict__ out, int L, int K) {
    __shared__ float ws[32];
    __shared__ int ds[32];
    int blk = blockIdx.x;
    int b = blk / L, t = blk % L;
    int d4 = threadIdx.x;            // 0..127 -> channels [4*d4, 4*d4+4)
    if (d4 < K) { ws[d4] = w[b * 32 + d4]; ds[d4] = dly[b * 32 + d4]; }
    __syncthreads();
    float4 s = make_float4(0.f, 0.f, 0.f, 0.f);
    for (int i = 0; i < K; i++) {
        int tt = t + ds[i]; if (tt >= L) tt -= L;
        float4 vv = *(const float4*)&v[((size_t)(b * L + tt)) * DM + d4 * 4];
        float wi = ws[i];
        s.x += wi * vv.x; s.y += wi * vv.y; s.z += wi * vv.z; s.w += wi * vv.w;
    }
    *(float4*)&out[((size_t)(b * L + t)) * DM + d4 * 4] = s;
}

// per-row layernorm over DM=512 channels; 128 threads, float4 per thread.
__global__ void __launch_bounds__(128) k_ln(const float* __restrict__ X,
                                            const float* __restrict__ g,
                                            const float* __restrict__ be,
                                            float* __restrict__ Y) {
    __shared__ float red[4];
    int row = blockIdx.x, tid = threadIdx.x;
    int lane = tid & 31, warp = tid >> 5;
    float4 xv = *(const float4*)&X[(size_t)row * DM + tid * 4];

    // mean
    float s = xv.x + xv.y + xv.z + xv.w;
#pragma unroll
    for (int o = 16; o > 0; o >>= 1) s += __shfl_down_sync(0xffffffffu, s, o);
    if (lane == 0) red[warp] = s;
    __syncthreads();
    float mu = (red[0] + red[1] + red[2] + red[3]) * (1.f / DM);
    __syncthreads();

    // variance
    float4 dv = make_float4(xv.x - mu, xv.y - mu, xv.z - mu, xv.w - mu);
    float v = dv.x * dv.x + dv.y * dv.y + dv.z * dv.z + dv.w * dv.w;
#pragma unroll
    for (int o = 16; o > 0; o >>= 1) v += __shfl_down_sync(0xffffffffu, v, o);
    if (lane == 0) red[warp] = v;
    __syncthreads();
    float inv = rsqrtf((red[0] + red[1] + red[2] + red[3]) * (1.f / DM) + 1e-5f);

    float4 gv = *(const float4*)&g[tid * 4];
    float4 bv = *(const float4*)&be[tid * 4];
    float4 yv = make_float4(dv.x * inv * gv.x + bv.x, dv.y * inv * gv.y + bv.y,
                            dv.z * inv * gv.z + bv.z, dv.w * inv * gv.w + bv.w);
    *(float4*)&Y[(size_t)row * DM + tid * 4] = yv;
}

// partial column sums over time -> cm (atomic accumulate; pre-zeroed),
// 128 threads x float4 channels
__global__ void __launch_bounds__(128) k_colsum(const float* __restrict__ Y,
                                                float* __restrict__ cm, int L) {
    int b = blockIdx.x, chunk = blockIdx.y, nch = gridDim.y;
    int d4 = threadIdx.x;
    float4 s = make_float4(0.f, 0.f, 0.f, 0.f);
    for (int t = chunk; t < L; t += nch) {
        float4 y = *(const float4*)&Y[((size_t)(b * L + t)) * DM + d4 * 4];
        s.x += y.x; s.y += y.y; s.z += y.z; s.w += y.w;
    }
    atomicAdd(&cm[b * DM + d4 * 4 + 0], s.x);
    atomicAdd(&cm[b * DM + d4 * 4 + 1], s.y);
    atomicAdd(&cm[b * DM + d4 * 4 + 2], s.z);
    atomicAdd(&cm[b * DM + d4 * 4 + 3], s.w);
}

// Y[b,t,:] -= cm[b,:]/L, float4 vectorized
__global__ void k_subcm(float* __restrict__ Y, const float* __restrict__ cm, int L) {
    size_t i4 = (size_t)blockIdx.x * blockDim.x + threadIdx.x;
    size_t total4 = (size_t)BATCH * L * DM / 4;
    if (i4 >= total4) return;
    int d4 = (int)(i4 % (DM / 4));
    int b = (int)(i4 / ((size_t)L * (DM / 4)));
    float4 y = *(float4*)&Y[i4 * 4];
    float4 c = *(const float4*)&cm[b * DM + d4 * 4];
    float invL = 1.f / (float)L;
    y.x -= c.x * invL; y.y -= c.y * invL; y.z -= c.z * invL; y.w -= c.w * invL;
    *(float4*)&Y[i4 * 4] = y;
}

// final: out[b,to,c] = (xh @ Wproj + bproj) + trend_init + circ_conv(tsum, Wtr) at t=to+LABEL
__global__ void __launch_bounds__(224) k_final(const float* __restrict__ xh,
                                               const float* __restrict__ tsum,
                                               const float* __restrict__ tdec,
                                               const float* __restrict__ Wtr,
                                               const float* __restrict__ Wp,
                                               const float* __restrict__ bp,
                                               float* __restrict__ out) {
    __shared__ float xs[DM];
    __shared__ float ts[3][DM];
    int blk = blockIdx.x;
    int b = blk / PRED, to = blk % PRED;
    int t = to + LABEL;
    int tid = threadIdx.x;
    for (int d = tid; d < DM; d += 224) xs[d] = xh[((size_t)(b * LDEC + t)) * DM + d];
    for (int w = 0; w < 3; w++) {
        int tt = (t - 1 + w + LDEC) % LDEC;
        for (int d = tid; d < DM; d += 224) ts[w][d] = tsum[((size_t)(b * LDEC + tt)) * DM + d];
    }
    __syncthreads();
    int c = tid >> 5, lane = tid & 31;
    float s = 0.f;
    for (int d = lane; d < DM; d += 32) {
        s += xs[d] * Wp[d * CC + c];
        s += ts[0][d] * Wtr[(0 * DM + d) * CC + c];
        s += ts[1][d] * Wtr[(1 * DM + d) * CC + c];
        s += ts[2][d] * Wtr[(2 * DM + d) * CC + c];
    }
    for (int o = 16; o > 0; o >>= 1) s += __shfl_down_sync(0xffffffffu, s, o);
    if (lane == 0)
        out[(b * PRED + to) * CC + c] = s + bp[c] + tdec[(b * LDEC + t) * CC + c];
}

// ---------------- host orchestration ----------------
extern "C" void kernel_launch(void* const* d_in, const int* in_sizes, int n_in,
                              void* d_out, int out_size) {
    const float* x_enc      = (const float*)d_in[0];
    const float* x_mark_enc = (const float*)d_in[1];
    const float* x_mark_dec = (const float*)d_in[3];
    const float* W_enc_emb  = (const float*)d_in[4];
    const float* W_mark_enc = (const float*)d_in[5];
    const float* W_dec_emb  = (const float*)d_in[6];
    const float* W_mark_dec = (const float*)d_in[7];
    const float* eW_attn    = (const float*)d_in[8];
    const float* eb_attn    = (const float*)d_in[9];
    const float* eW1        = (const float*)d_in[10];
    const float* eW2        = (const float*)d_in[11];
    const float* eg         = (const float*)d_in[12];
    const float* ebeta      = (const float*)d_in[13];
    const float* sW         = (const float*)d_in[14];
    const float* sb         = (const float*)d_in[15];
    const float* cW         = (const float*)d_in[16];
    const float* cb         = (const float*)d_in[17];
    const float* dW1        = (const float*)d_in[18];
    const float* dW2        = (const float*)d_in[19];
    const float* W_trend    = (const float*)d_in[20];
    const float* dg         = (const float*)d_in[21];
    const float* dbeta      = (const float*)d_in[22];
    const float* Wproj      = (const float*)d_in[23];
    const float* bproj      = (const float*)d_in[24];
    float* out = (float*)d_out;

    void* p;
    float *x, *sum, *q, *k, *v, *agg, *enc, *ffn, *tsum, *mc, *wts, *cm, *m7, *s7, *t7, *sdec, *tdec, *mdec;
    int* dly;
    cudaGetSymbolAddress(&p, g_x);    x    = (float*)p;
    cudaGetSymbolAddress(&p, g_sum);  sum  = (float*)p;
    cudaGetSymbolAddress(&p, g_q);    q    = (float*)p;
    cudaGetSymbolAddress(&p, g_k);    k    = (float*)p;
    cudaGetSymbolAddress(&p, g_v);    v    = (float*)p;
    cudaGetSymbolAddress(&p, g_agg);  agg  = (float*)p;
    cudaGetSymbolAddress(&p, g_enc);  enc  = (float*)p;
    cudaGetSymbolAddress(&p, g_ffn);  ffn  = (float*)p;
    cudaGetSymbolAddress(&p, g_tsum); tsum = (float*)p;
    cudaGetSymbolAddress(&p, g_mc);   mc   = (float*)p;
    cudaGetSymbolAddress(&p, g_wts);  wts  = (float*)p;
    cudaGetSymbolAddress(&p, g_dly);  dly  = (int*)p;
    cudaGetSymbolAddress(&p, g_cm);   cm   = (float*)p;
    cudaGetSymbolAddress(&p, g_m7);   m7   = (float*)p;
    cudaGetSymbolAddress(&p, g_s7);   s7   = (float*)p;
    cudaGetSymbolAddress(&p, g_t7);   t7   = (float*)p;
    cudaGetSymbolAddress(&p, g_sdec); sdec = (float*)p;
    cudaGetSymbolAddress(&p, g_tdec); tdec = (float*)p;
    cudaGetSymbolAddress(&p, g_mdec); mdec = (float*)p;

    const int rowsE = BATCH * LE;     // 16384
    const int rowsD = BATCH * LDEC;   // 18944
    const int KE = (int)(3.0 * log(512.0));  // 18
    const int KD = (int)(3.0 * log(592.0));  // 19

    auto GN = [](int M, int N) { return dim3((unsigned)((N + 127) / 128), (unsigned)((M + 127) / 128), 1); };

    // ---- series_decomp of x_enc + decoder inits ----
    k_mean7<<<(BATCH * CC * 32 + 255) / 256, 256>>>(x_enc, m7);
    {
        int n = BATCH * LE * CC;
        k_decomp7<<<(n + 255) / 256, 256>>>(x_enc, s7, t7);
    }
    {
        int n = BATCH * LDEC * CC;
        k_build_dec<<<(n + 255) / 256, 256>>>(s7, t7, m7, sdec, tdec);
        int nm = BATCH * LDEC * MMK;
        k_build_mark<<<(nm + 255) / 256, 256>>>(x_mark_enc, x_mark_dec, mdec);
    }

    // ---- attention helper: writes outBuf = resBuf + attn_out ----
    // Lk = valid K rows per batch (== L unless kvPad).
    auto attn = [&](const float* qin, const float* kin, const float* vin,
                    int rowsQ, int rowsKV, int L, int Lk, int Kk,
                    const float* W, const float* bb, bool kvPad,
                    const float* resBuf, float* outBuf) {
        gemm_nn<<<GN(rowsQ, DM), 256>>>(qin, W, bb, nullptr, q, rowsQ, DM, DM, 1, 1, 0);
        if (kvPad) {
            int nPad4 = BATCH * (LDEC - LE) * (DM / 4);
            k_zero_pad<<<(nPad4 + 255) / 256, 256>>>(k, LE, LDEC);
            k_zero_pad<<<(nPad4 + 255) / 256, 256>>>(v, LE, LDEC);
            gemm_nn<<<GN(rowsKV, DM), 256>>>(kin, W + DM * DM, bb + DM, nullptr, k, rowsKV, DM, DM, LE, LDEC, 0);
            gemm_nn<<<GN(rowsKV, DM), 256>>>(vin, W + 2 * DM * DM, bb + 2 * DM, nullptr, v, rowsKV, DM, DM, LE, LDEC, 0);
        } else {
            gemm_nn<<<GN(rowsKV, DM), 256>>>(kin, W + DM * DM, bb + DM, nullptr, k, rowsKV, DM, DM, 1, 1, 0);
            gemm_nn<<<GN(rowsKV, DM), 256>>>(vin, W + 2 * DM * DM, bb + 2 * DM, nullptr, v, rowsKV, DM, DM, 1, 1, 0);
        }
        int n = BATCH * L;
        k_zero<<<(n + 255) / 256, 256>>>(mc, n);
        gemm_nt_fold<<<dim3((unsigned)((Lk + 127) / 128), (unsigned)((L + 127) / 128), BATCH), 256>>>(q, k, mc, L, Lk, DM);
        k_topk<<<BATCH, 256>>>(mc, wts, dly, L, Kk);
        k_agg<<<BATCH * L, 128>>>(v, wts, dly, agg, L, Kk);
        gemm_nn<<<GN(rowsQ, DM), 256>>>(agg, W + 3 * DM * DM, bb + 3 * DM, resBuf, outBuf, rowsQ, DM, DM, 1, 1, 0);
    };

    const int nSW = BATCH * DM * NCH;

    // ================= encoder =================
    k_embed<<<BATCH * (LE / 8), 512>>>(x_enc, x_mark_enc, W_enc_emb, W_mark_enc, x, LE);

    for (int l = 0; l < 2; l++) {
        const float* W  = eW_attn + (size_t)l * 4 * DM * DM;
        const float* bb = eb_attn + (size_t)l * 4 * DM;
        attn(x, x, x, rowsE, rowsE, LE, LE, KE, W, bb, false, x, sum);   // sum = x + attn(x)
        k_decomp_sw<<<(nSW + 255) / 256, 256>>>(sum, x, tsum, LE, 0);
        gemm_nn<<<GN(rowsE, DFF), 256>>>(x, eW1 + (size_t)l * DM * DFF, nullptr, nullptr, ffn, rowsE, DFF, DM, 1, 1, 1);
        gemm_nn<<<GN(rowsE, DM), 256>>>(ffn, eW2 + (size_t)l * DFF * DM, nullptr, x, sum, rowsE, DM, DFF, 1, 1, 0); // sum = x + ffn
        k_decomp_sw<<<(nSW + 255) / 256, 256>>>(sum, x, tsum, LE, 0);
    }
    // enc_out = my_layernorm(x, eg, ebeta)
    k_ln<<<rowsE, 128>>>(x, eg, ebeta, enc);
    {
        int n = BATCH * DM;
        k_zero<<<(n + 255) / 256, 256>>>(cm, n);
        k_colsum<<<dim3(BATCH, 8), 128>>>(enc, cm, LE);
        int n4 = rowsE * DM / 4;
        k_subcm<<<(n4 + 255) / 256, 256>>>(enc, cm, LE);
    }

    // ================= decoder =================
    k_embed<<<BATCH * (LDEC / 8), 512>>>(sdec, mdec, W_dec_emb, W_mark_dec, x, LDEC);

    // self attention
    attn(x, x, x, rowsD, rowsD, LDEC, LDEC, KD, sW, sb, false, x, sum);
    k_decomp_sw<<<(nSW + 255) / 256, 256>>>(sum, x, tsum, LDEC, 1);   // write t1

    // cross attention (K/V from encoder output, zero-padded 512->592; only
    // rows < LE are valid K/V rows)
    attn(x, enc, enc, rowsD, rowsE, LDEC, LE, KD, cW, cb, true, x, sum);
    k_decomp_sw<<<(nSW + 255) / 256, 256>>>(sum, x, tsum, LDEC, 2);   // += t2

    // FFN
    gemm_nn<<<GN(rowsD, DFF), 256>>>(x, dW1, nullptr, nullptr, ffn, rowsD, DFF, DM, 1, 1, 1);
    gemm_nn<<<GN(rowsD, DM), 256>>>(ffn, dW2, nullptr, x, sum, rowsD, DM, DFF, 1, 1, 0);
    k_decomp_sw<<<(nSW + 255) / 256, 256>>>(sum, x, tsum, LDEC, 2);   // += t3

    // my_layernorm(x, dg, dbeta) -> sum (reused as xh buffer)
    k_ln<<<rowsD, 128>>>(x, dg, dbeta, sum);
    {
        int n = BATCH * DM;
        k_zero<<<(n + 255) / 256, 256>>>(cm, n);
        k_colsum<<<dim3(BATCH, 8), 128>>>(sum, cm, LDEC);
        int n4 = rowsD * DM / 4;
        k_subcm<<<(n4 + 255) / 256, 256>>>(sum, cm, LDEC);
    }

    // final: seasonal projection + trend conv + slice
    k_final<<<BATCH * PRED, 224>>>(sum, tsum, tdec, W_trend, Wproj, bproj, out);
}

// round 13
// speedup vs baseline: 1.5706x; 1.5706x over previous
#include <cuda_runtime.h>
#include <cuda_bf16.h>
#include <math.h>
#include <stdint.h>

// ---------------- problem constants ----------------
#define BATCH 32
#define DM    512
#define DFF   2048
#define LE    512      // encoder length
#define LDEC  592      // decoder length (label 256 + pred 336)
#define CC    7
#define MMK   4
#define LABEL 256
#define PRED  336
#define KSZ   25
#define KHALF 12
#define NCH   8        // time chunks for sliding-window decomp

// ---------------- device scratch (static, no allocation) ----------------
__device__ float g_x   [BATCH*LDEC*DM];
__device__ float g_sum [BATCH*LDEC*DM];
__device__ float g_q   [BATCH*LDEC*DM];
__device__ float g_k   [BATCH*LDEC*DM];
__device__ float g_v   [BATCH*LDEC*DM];
__device__ float g_agg [BATCH*LDEC*DM];
__device__ float g_enc [BATCH*LE*DM];
__device__ float g_ffn [BATCH*LDEC*DFF];
__device__ float g_tsum[BATCH*LDEC*DM];
__device__ float g_mc  [BATCH*LDEC];
__device__ float g_wts [BATCH*32];
__device__ int   g_dly [BATCH*32];
__device__ float g_cm  [BATCH*DM];
__device__ float g_m7  [BATCH*CC];
__device__ float g_s7  [BATCH*LE*CC];
__device__ float g_t7  [BATCH*LE*CC];
__device__ float g_sdec[BATCH*LDEC*CC];
__device__ float g_tdec[BATCH*LDEC*CC];
__device__ float g_mdec[BATCH*LDEC*MMK];

// ================= mma.sync split-bf16 GEMM (baseline ISA, sm_80+) ==========
// C[M,N] = A[M,K] @ B[K,N] (+bias)(+res)(+gelu), fp32 in/out.
// Split: A = Ah + Al (bf16), B = Bh + Bl; D += Ah*Bh + Ah*Bl + Al*Bh (fp32 acc).
// 128x128 tile, BK=32, 256 threads (8 warps, 2x4), warp tile 64x32 (4x4 frags
// of m16n8k16). SMEM rows stride 40 bf16 (80B = 20 banks -> conflict-free
// fragment loads for bank pattern (20*g + tig) mod 32).
// REQUIRES M % 128 == 0, N % 128 == 0, K % 32 == 0.
#define PADK 40

__device__ __forceinline__ void mma_bf16(float& d0, float& d1, float& d2, float& d3,
                                         uint32_t a0, uint32_t a1, uint32_t a2, uint32_t a3,
                                         uint32_t b0, uint32_t b1) {
    asm volatile(
        "mma.sync.aligned.m16n8k16.row.col.f32.bf16.bf16.f32 "
        "{%0,%1,%2,%3}, {%4,%5,%6,%7}, {%8,%9}, {%0,%1,%2,%3};"
        : "+f"(d0), "+f"(d1), "+f"(d2), "+f"(d3)
        : "r"(a0), "r"(a1), "r"(a2), "r"(a3), "r"(b0), "r"(b1));
}

__device__ __forceinline__ void split_pack(float x0, float x1,
                                           uint32_t& hi, uint32_t& lo) {
    __nv_bfloat16 h0 = __float2bfloat16(x0), h1 = __float2bfloat16(x1);
    float l0 = x0 - __bfloat162float(h0), l1 = x1 - __bfloat162float(h1);
    __nv_bfloat162 hp; hp.x = h0; hp.y = h1;
    __nv_bfloat162 lp; lp.x = __float2bfloat16(l0); lp.y = __float2bfloat16(l1);
    hi = *(uint32_t*)&hp;
    lo = *(uint32_t*)&lp;
}

__global__ void __launch_bounds__(256) mma_gemm(
    const float* __restrict__ A, const float* __restrict__ B,
    const float* __restrict__ bias, const float* __restrict__ res,
    float* __restrict__ C, int M, int N, int K, int gelu)
{
    __shared__ __align__(16) __nv_bfloat16 aHi[128 * PADK];
    __shared__ __align__(16) __nv_bfloat16 aLo[128 * PADK];
    __shared__ __align__(16) __nv_bfloat16 bHi[128 * PADK];
    __shared__ __align__(16) __nv_bfloat16 bLo[128 * PADK];
    uint32_t* uaHi = (uint32_t*)aHi;
    uint32_t* uaLo = (uint32_t*)aLo;
    uint32_t* ubHi = (uint32_t*)bHi;
    uint32_t* ubLo = (uint32_t*)bLo;

    int tid = threadIdx.x;
    int warp = tid >> 5, lane = tid & 31;
    int mw = warp >> 2, nw = warp & 3;     // warp grid 2 x 4
    int g = lane >> 2, tig = lane & 3;
    int m0 = blockIdx.y * 128, n0 = blockIdx.x * 128;

    float acc[4][4][4];
#pragma unroll
    for (int m = 0; m < 4; m++)
#pragma unroll
        for (int n = 0; n < 4; n++)
#pragma unroll
            for (int i = 0; i < 4; i++) acc[m][n][i] = 0.f;

    int arow = tid >> 1, ahalf = tid & 1;   // A loader: row 0..127, k half
    int bnn = tid >> 1, bhalf = tid & 1;    // B loader: col 0..127, k half

    for (int k0 = 0; k0 < K; k0 += 32) {
        // ---- stage A[m0+row][k0+half*16 .. +16]
        {
            const float* src = A + (size_t)(m0 + arow) * K + k0 + ahalf * 16;
            float4 f0 = *(const float4*)(src);
            float4 f1 = *(const float4*)(src + 4);
            float4 f2 = *(const float4*)(src + 8);
            float4 f3 = *(const float4*)(src + 12);
            float xs[16] = {f0.x, f0.y, f0.z, f0.w, f1.x, f1.y, f1.z, f1.w,
                            f2.x, f2.y, f2.z, f2.w, f3.x, f3.y, f3.z, f3.w};
            int base = arow * 20 + ahalf * 8;
#pragma unroll
            for (int j = 0; j < 8; j++) {
                uint32_t hw, lw;
                split_pack(xs[2 * j], xs[2 * j + 1], hw, lw);
                uaHi[base + j] = hw;
                uaLo[base + j] = lw;
            }
        }
        // ---- stage B[k0+half*16 + j][n0+nn] transposed (n-major, k contiguous)
        {
            float xs[16];
#pragma unroll
            for (int j = 0; j < 16; j++)
                xs[j] = B[(size_t)(k0 + bhalf * 16 + j) * N + n0 + bnn];
            int base = bnn * 20 + bhalf * 8;
#pragma unroll
            for (int j = 0; j < 8; j++) {
                uint32_t hw, lw;
                split_pack(xs[2 * j], xs[2 * j + 1], hw, lw);
                ubHi[base + j] = hw;
                ubLo[base + j] = lw;
            }
        }
        __syncthreads();

        // ---- compute: 2 k-steps of 16
#pragma unroll
        for (int s = 0; s < 2; s++) {
            int ko = 8 * s + tig;
            uint32_t Bh[4][2], Bl[4][2];
#pragma unroll
            for (int n = 0; n < 4; n++) {
                int cb = (nw * 32 + n * 8 + g) * 20 + ko;
                Bh[n][0] = ubHi[cb];     Bh[n][1] = ubHi[cb + 4];
                Bl[n][0] = ubLo[cb];     Bl[n][1] = ubLo[cb + 4];
            }
#pragma unroll
            for (int m = 0; m < 4; m++) {
                int r0 = (mw * 64 + m * 16 + g) * 20 + ko;
                int r1 = r0 + 8 * 20;
                uint32_t Ah0 = uaHi[r0], Ah1 = uaHi[r1];
                uint32_t Ah2 = uaHi[r0 + 4], Ah3 = uaHi[r1 + 4];
                uint32_t Al0 = uaLo[r0], Al1 = uaLo[r1];
                uint32_t Al2 = uaLo[r0 + 4], Al3 = uaLo[r1 + 4];
#pragma unroll
                for (int n = 0; n < 4; n++) {
                    mma_bf16(acc[m][n][0], acc[m][n][1], acc[m][n][2], acc[m][n][3],
                             Ah0, Ah1, Ah2, Ah3, Bh[n][0], Bh[n][1]);
                    mma_bf16(acc[m][n][0], acc[m][n][1], acc[m][n][2], acc[m][n][3],
                             Ah0, Ah1, Ah2, Ah3, Bl[n][0], Bl[n][1]);
                    mma_bf16(acc[m][n][0], acc[m][n][1], acc[m][n][2], acc[m][n][3],
                             Al0, Al1, Al2, Al3, Bh[n][0], Bh[n][1]);
                }
            }
        }
        __syncthreads();
    }

    // ---- epilogue: c0=(g,2tig) c1=(g,2tig+1) c2=(g+8,2tig) c3=(g+8,2tig+1)
#pragma unroll
    for (int m = 0; m < 4; m++) {
        int row0 = m0 + mw * 64 + m * 16 + g;
        int row1 = row0 + 8;
#pragma unroll
        for (int n = 0; n < 4; n++) {
            int col = n0 + nw * 32 + n * 8 + 2 * tig;
            float v0 = acc[m][n][0], v1 = acc[m][n][1];
            float v2 = acc[m][n][2], v3 = acc[m][n][3];
            if (bias) {
                float2 bb = *(const float2*)&bias[col];
                v0 += bb.x; v1 += bb.y; v2 += bb.x; v3 += bb.y;
            }
            if (res) {
                float2 r0 = *(const float2*)&res[(size_t)row0 * N + col];
                float2 r1 = *(const float2*)&res[(size_t)row1 * N + col];
                v0 += r0.x; v1 += r0.y; v2 += r1.x; v3 += r1.y;
            }
            if (gelu) {
                v0 *= normcdff(v0); v1 *= normcdff(v1);
                v2 *= normcdff(v2); v3 *= normcdff(v3);
            }
            *(float2*)&C[(size_t)row0 * N + col] = make_float2(v0, v1);
            *(float2*)&C[(size_t)row1 * N + col] = make_float2(v2, v3);
        }
    }
}

// ---------------- fp32 GEMM (SIMT; used for row-remap projections) ----------
__global__ void __launch_bounds__(256) gemm_nn(
    const float* __restrict__ A, const float* __restrict__ B,
    const float* __restrict__ bias, const float* __restrict__ res,
    float* __restrict__ C,
    int M, int N, int K, int rpbIn, int rpbOut, int gelu)
{
    __shared__ float As[2][16][132];
    __shared__ float Bs[2][16][132];
    int tid = threadIdx.x;
    int tx = tid & 15, ty = tid >> 4;
    int m0 = blockIdx.y * 128, n0 = blockIdx.x * 128;

    int arow = tid >> 2;
    int acol = (tid & 3) * 4;
    int brow = tid >> 5;
    int bcol = (tid & 31) * 4;
    const float* Ap0 = A + (size_t)(m0 + arow) * K + acol;
    const float* Ap1 = Ap0 + (size_t)64 * K;
    const float* Bp0 = B + (size_t)brow * N + n0 + bcol;
    const float* Bp1 = Bp0 + (size_t)8 * N;

    float4 a0v, a1v, b0v, b1v;
    float acc[8][8];
#pragma unroll
    for (int i = 0; i < 8; i++)
#pragma unroll
        for (int j = 0; j < 8; j++) acc[i][j] = 0.f;

    a0v = *(const float4*)(Ap0);
    a1v = *(const float4*)(Ap1);
    b0v = *(const float4*)(Bp0);
    b1v = *(const float4*)(Bp1);
    {
        As[0][acol + 0][arow] = a0v.x; As[0][acol + 1][arow] = a0v.y;
        As[0][acol + 2][arow] = a0v.z; As[0][acol + 3][arow] = a0v.w;
        As[0][acol + 0][arow + 64] = a1v.x; As[0][acol + 1][arow + 64] = a1v.y;
        As[0][acol + 2][arow + 64] = a1v.z; As[0][acol + 3][arow + 64] = a1v.w;
        *(float4*)&Bs[0][brow][bcol]     = b0v;
        *(float4*)&Bs[0][brow + 8][bcol] = b1v;
    }
    __syncthreads();

    int buf = 0;
    for (int k0 = 0; k0 < K; k0 += 16) {
        bool more = (k0 + 16 < K);
        if (more) {
            a0v = *(const float4*)(Ap0 + k0 + 16);
            a1v = *(const float4*)(Ap1 + k0 + 16);
            b0v = *(const float4*)(Bp0 + (size_t)(k0 + 16) * N);
            b1v = *(const float4*)(Bp1 + (size_t)(k0 + 16) * N);
        }
#pragma unroll
        for (int k = 0; k < 16; k++) {
            float4 x0 = *(const float4*)&As[buf][k][ty * 4];
            float4 x1 = *(const float4*)&As[buf][k][64 + ty * 4];
            float4 y0 = *(const float4*)&Bs[buf][k][tx * 4];
            float4 y1 = *(const float4*)&Bs[buf][k][64 + tx * 4];
            float av[8] = {x0.x, x0.y, x0.z, x0.w, x1.x, x1.y, x1.z, x1.w};
            float bv[8] = {y0.x, y0.y, y0.z, y0.w, y1.x, y1.y, y1.z, y1.w};
#pragma unroll
            for (int i = 0; i < 8; i++)
#pragma unroll
                for (int j = 0; j < 8; j++) acc[i][j] += av[i] * bv[j];
        }
        if (more) {
            int nb = buf ^ 1;
            As[nb][acol + 0][arow] = a0v.x; As[nb][acol + 1][arow] = a0v.y;
            As[nb][acol + 2][arow] = a0v.z; As[nb][acol + 3][arow] = a0v.w;
            As[nb][acol + 0][arow + 64] = a1v.x; As[nb][acol + 1][arow + 64] = a1v.y;
            As[nb][acol + 2][arow + 64] = a1v.z; As[nb][acol + 3][arow + 64] = a1v.w;
            *(float4*)&Bs[nb][brow][bcol]     = b0v;
            *(float4*)&Bs[nb][brow + 8][bcol] = b1v;
            __syncthreads();
            buf = nb;
        }
    }

    float4 bia0 = make_float4(0.f, 0.f, 0.f, 0.f), bia1 = bia0;
    if (bias) {
        bia0 = *(const float4*)&bias[n0 + tx * 4];
        bia1 = *(const float4*)&bias[n0 + 64 + tx * 4];
    }
#pragma unroll
    for (int ri = 0; ri < 8; ri++) {
        int gm = m0 + ((ri >> 2) * 64) + ty * 4 + (ri & 3);
        int orow = gm;
        if (rpbIn != rpbOut) orow = (gm / rpbIn) * rpbOut + (gm % rpbIn);
        float4 c0 = make_float4(acc[ri][0] + bia0.x, acc[ri][1] + bia0.y,
                                acc[ri][2] + bia0.z, acc[ri][3] + bia0.w);
        float4 c1 = make_float4(acc[ri][4] + bia1.x, acc[ri][5] + bia1.y,
                                acc[ri][6] + bia1.z, acc[ri][7] + bia1.w);
        if (res) {
            float4 r0 = *(const float4*)&res[(size_t)orow * N + n0 + tx * 4];
            float4 r1 = *(const float4*)&res[(size_t)orow * N + n0 + 64 + tx * 4];
            c0.x += r0.x; c0.y += r0.y; c0.z += r0.z; c0.w += r0.w;
            c1.x += r1.x; c1.y += r1.y; c1.z += r1.z; c1.w += r1.w;
        }
        if (gelu) {
            c0.x *= normcdff(c0.x); c0.y *= normcdff(c0.y);
            c0.z *= normcdff(c0.z); c0.w *= normcdff(c0.w);
            c1.x *= normcdff(c1.x); c1.y *= normcdff(c1.y);
            c1.z *= normcdff(c1.z); c1.w *= normcdff(c1.w);
        }
        *(float4*)&C[(size_t)orow * N + n0 + tx * 4]      = c0;
        *(float4*)&C[(size_t)orow * N + n0 + 64 + tx * 4] = c1;
    }
}

// ---------------- batched NT GEMM + diagonal fold ----------------
__global__ void __launch_bounds__(256) gemm_nt_fold(
    const float* __restrict__ Q, const float* __restrict__ Km,
    float* __restrict__ mc, int L, int Lk, int D)
{
    __shared__ float As[2][16][132];
    __shared__ float Bs[2][16][132];
    __shared__ float bins[255];
    int b = blockIdx.z;
    const float* Ab = Q  + (size_t)b * L * D;
    const float* Bb = Km + (size_t)b * L * D;
    int tid = threadIdx.x;
    int tx = tid & 15, ty = tid >> 4;
    int m0 = blockIdx.y * 128, n0 = blockIdx.x * 128;

    int row = tid >> 2;
    int col4 = (tid & 3) * 4;
    bool aok0 = (m0 + row)      < L;
    bool aok1 = (m0 + row + 64) < L;
    bool bok0 = (n0 + row)      < Lk;
    bool bok1 = (n0 + row + 64) < Lk;
    const float* Ap0 = Ab + (size_t)(m0 + row) * D + col4;
    const float* Ap1 = Ap0 + (size_t)64 * D;
    const float* Bp0 = Bb + (size_t)(n0 + row) * D + col4;
    const float* Bp1 = Bp0 + (size_t)64 * D;

    float4 zf = make_float4(0.f, 0.f, 0.f, 0.f);
    float4 a0v, a1v, b0v, b1v;
    float acc[8][8];
#pragma unroll
    for (int i = 0; i < 8; i++)
#pragma unroll
        for (int j = 0; j < 8; j++) acc[i][j] = 0.f;

    a0v = aok0 ? *(const float4*)(Ap0) : zf;
    a1v = aok1 ? *(const float4*)(Ap1) : zf;
    b0v = bok0 ? *(const float4*)(Bp0) : zf;
    b1v = bok1 ? *(const float4*)(Bp1) : zf;
    {
        As[0][col4 + 0][row] = a0v.x; As[0][col4 + 1][row] = a0v.y;
        As[0][col4 + 2][row] = a0v.z; As[0][col4 + 3][row] = a0v.w;
        As[0][col4 + 0][row + 64] = a1v.x; As[0][col4 + 1][row + 64] = a1v.y;
        As[0][col4 + 2][row + 64] = a1v.z; As[0][col4 + 3][row + 64] = a1v.w;
        Bs[0][col4 + 0][row] = b0v.x; Bs[0][col4 + 1][row] = b0v.y;
        Bs[0][col4 + 2][row] = b0v.z; Bs[0][col4 + 3][row] = b0v.w;
        Bs[0][col4 + 0][row + 64] = b1v.x; Bs[0][col4 + 1][row + 64] = b1v.y;
        Bs[0][col4 + 2][row + 64] = b1v.z; Bs[0][col4 + 3][row + 64] = b1v.w;
    }
    __syncthreads();

    int buf = 0;
    for (int k0 = 0; k0 < D; k0 += 16) {
        bool more = (k0 + 16 < D);
        if (more) {
            a0v = aok0 ? *(const float4*)(Ap0 + k0 + 16) : zf;
            a1v = aok1 ? *(const float4*)(Ap1 + k0 + 16) : zf;
            b0v = bok0 ? *(const float4*)(Bp0 + k0 + 16) : zf;
            b1v = bok1 ? *(const float4*)(Bp1 + k0 + 16) : zf;
        }
#pragma unroll
        for (int k = 0; k < 16; k++) {
            float4 x0 = *(const float4*)&As[buf][k][ty * 4];
            float4 x1 = *(const float4*)&As[buf][k][64 + ty * 4];
            float4 y0 = *(const float4*)&Bs[buf][k][tx * 4];
            float4 y1 = *(const float4*)&Bs[buf][k][64 + tx * 4];
            float av[8] = {x0.x, x0.y, x0.z, x0.w, x1.x, x1.y, x1.z, x1.w};
            float bv[8] = {y0.x, y0.y, y0.z, y0.w, y1.x, y1.y, y1.z, y1.w};
#pragma unroll
            for (int i = 0; i < 8; i++)
#pragma unroll
                for (int j = 0; j < 8; j++) acc[i][j] += av[i] * bv[j];
        }
        if (more) {
            int nb = buf ^ 1;
            As[nb][col4 + 0][row] = a0v.x; As[nb][col4 + 1][row] = a0v.y;
            As[nb][col4 + 2][row] = a0v.z; As[nb][col4 + 3][row] = a0v.w;
            As[nb][col4 + 0][row + 64] = a1v.x; As[nb][col4 + 1][row + 64] = a1v.y;
            As[nb][col4 + 2][row + 64] = a1v.z; As[nb][col4 + 3][row + 64] = a1v.w;
            Bs[nb][col4 + 0][row] = b0v.x; Bs[nb][col4 + 1][row] = b0v.y;
            Bs[nb][col4 + 2][row] = b0v.z; Bs[nb][col4 + 3][row] = b0v.w;
            Bs[nb][col4 + 0][row + 64] = b1v.x; Bs[nb][col4 + 1][row + 64] = b1v.y;
            Bs[nb][col4 + 2][row + 64] = b1v.z; Bs[nb][col4 + 3][row + 64] = b1v.w;
            __syncthreads();
            buf = nb;
        }
    }

    __syncthreads();
    for (int i = tid; i < 255; i += 256) bins[i] = 0.f;
    __syncthreads();

    bool fullTile = (m0 + 128 <= L) && (n0 + 128 <= Lk);
    if (fullTile) {
        float tb[3][7];
#pragma unroll
        for (int i = 0; i < 3; i++)
#pragma unroll
            for (int j = 0; j < 7; j++) tb[i][j] = 0.f;
#pragma unroll
        for (int ri = 0; ri < 8; ri++)
#pragma unroll
            for (int ci = 0; ci < 8; ci++)
                tb[(ri >> 2) - (ci >> 2) + 1][(ri & 3) - (ci & 3) + 3] += acc[ri][ci];
        int baseOff = (ty - tx) * 4 + 127;
#pragma unroll
        for (int i = 0; i < 3; i++)
#pragma unroll
            for (int j = 0; j < 7; j++)
                atomicAdd(&bins[baseOff + 64 * (i - 1) + (j - 3)], tb[i][j]);
    } else {
#pragma unroll
        for (int ri = 0; ri < 8; ri++) {
            int lm = ((ri >> 2) * 64) + ty * 4 + (ri & 3);
            if (m0 + lm >= L) continue;
#pragma unroll
            for (int ci = 0; ci < 8; ci++) {
                int ln = ((ci >> 2) * 64) + tx * 4 + (ci & 3);
                if (n0 + ln < Lk) atomicAdd(&bins[lm - ln + 127], acc[ri][ci]);
            }
        }
    }
    __syncthreads();
    int base = m0 - n0;
    for (int i = tid; i < 255; i += 256) {
        float vbin = bins[i];
        if (vbin != 0.f) {
            int tau = base + i - 127;
            tau %= L; if (tau < 0) tau += L;
            atomicAdd(&mc[b * L + tau], vbin * (1.f / DM));
        }
    }
}

// ---------------- small kernels ----------------
__global__ void __launch_bounds__(256) k_mean7(const float* __restrict__ x,
                                               float* __restrict__ m7) {
    int wid = (blockIdx.x * blockDim.x + threadIdx.x) >> 5;
    int lane = threadIdx.x & 31;
    if (wid >= BATCH * CC) return;
    int b = wid / CC, c = wid % CC;
    float s = 0.f;
    for (int i = lane; i < LE; i += 32) s += x[(b * LE + i) * CC + c];
#pragma unroll
    for (int o = 16; o > 0; o >>= 1) s += __shfl_down_sync(0xffffffffu, s, o);
    if (lane == 0) m7[wid] = s / LE;
}

__global__ void k_decomp7(const float* __restrict__ x, float* __restrict__ seas,
                          float* __restrict__ tr) {
    int idx = blockIdx.x * blockDim.x + threadIdx.x;
    if (idx >= BATCH * LE * CC) return;
    int c = idx % CC, t = (idx / CC) % LE, b = idx / (CC * LE);
    float s = 0.f;
#pragma unroll
    for (int u = -KHALF; u <= KHALF; u++) {
        int tt = t + u; tt = tt < 0 ? 0 : (tt >= LE ? LE - 1 : tt);
        s += x[(b * LE + tt) * CC + c];
    }
    float m = s * (1.f / KSZ);
    seas[idx] = x[idx] - m;
    tr[idx] = m;
}

__global__ void k_build_dec(const float* __restrict__ s7, const float* __restrict__ t7,
                            const float* __restrict__ m7, float* __restrict__ sdec,
                            float* __restrict__ tdec) {
    int idx = blockIdx.x * blockDim.x + threadIdx.x;
    if (idx >= BATCH * LDEC * CC) return;
    int c = idx % CC, t = (idx / CC) % LDEC, b = idx / (CC * LDEC);
    if (t < LABEL) {
        int src = (b * LE + (LE - LABEL) + t) * CC + c;
        sdec[idx] = s7[src];
        tdec[idx] = t7[src];
    } else {
        sdec[idx] = 0.f;
        tdec[idx] = m7[b * CC + c];
    }
}

__global__ void k_build_mark(const float* __restrict__ me, const float* __restrict__ md,
                             float* __restrict__ out) {
    int idx = blockIdx.x * blockDim.x + threadIdx.x;
    if (idx >= BATCH * LDEC * MMK) return;
    int m = idx % MMK, t = (idx / MMK) % LDEC, b = idx / (MMK * LDEC);
    out[idx] = (t < LABEL) ? me[(b * LE + (LE - LABEL) + t) * MMK + m]
                           : md[(b * PRED + (t - LABEL)) * MMK + m];
}

__global__ void __launch_bounds__(512) k_embed(
    const float* __restrict__ x, const float* __restrict__ mark,
    const float* __restrict__ Wc, const float* __restrict__ Wm,
    float* __restrict__ out, int L) {
    __shared__ float xs[10 * CC];
    __shared__ float ms[8 * MMK];
    int blk = blockIdx.x;
    int nch = L >> 3;
    int b = blk / nch, t0 = (blk % nch) << 3;
    int tid = threadIdx.x;
    if (tid < 10 * CC) {
        int r = tid / CC, c = tid % CC;
        int tt = (t0 - 1 + r + L) % L;
        xs[tid] = x[(b * L + tt) * CC + c];
    } else if (tid < 10 * CC + 8 * MMK) {
        int q = tid - 10 * CC;
        int r = q / MMK, m = q % MMK;
        ms[q] = mark[(b * L + t0 + r) * MMK + m];
    }
    __syncthreads();
    int o = tid;
    float wc[3 * CC], wm[MMK];
#pragma unroll
    for (int i = 0; i < 3 * CC; i++) wc[i] = Wc[i * DM + o];
#pragma unroll
    for (int m = 0; m < MMK; m++) wm[m] = Wm[m * DM + o];
#pragma unroll
    for (int r = 0; r < 8; r++) {
        float s = 0.f;
#pragma unroll
        for (int w = 0; w < 3; w++)
#pragma unroll
            for (int c = 0; c < CC; c++)
                s += xs[(r + w) * CC + c] * wc[w * CC + c];
#pragma unroll
        for (int m = 0; m < MMK; m++) s += ms[r * MMK + m] * wm[m];
        out[((size_t)(b * L + t0 + r)) * DM + o] = s;
    }
}

__global__ void k_zero(float* __restrict__ p, int n) {
    int i = blockIdx.x * blockDim.x + threadIdx.x;
    int n4 = n >> 2;
    if (i < n4) {
        ((float4*)p)[i] = make_float4(0.f, 0.f, 0.f, 0.f);
    } else {
        int r = n4 * 4 + (i - n4);
        if (r < n) p[r] = 0.f;
    }
}

__global__ void k_zero_pad(float* __restrict__ p, int r0, int rpb) {
    int idx = blockIdx.x * blockDim.x + threadIdx.x;
    int nPadRows = rpb - r0;
    if (idx >= BATCH * nPadRows * (DM / 4)) return;
    int d4 = idx % (DM / 4);
    int rest = idx / (DM / 4);
    int r = rest % nPadRows;
    int b = rest / nPadRows;
    *(float4*)&p[((size_t)(b * rpb + r0 + r)) * DM + d4 * 4] =
        make_float4(0.f, 0.f, 0.f, 0.f);
}

__global__ void k_decomp_sw(const float* __restrict__ S, float* __restrict__ seas,
                            float* __restrict__ trend, int L, int mode) {
    int idx = blockIdx.x * blockDim.x + threadIdx.x;
    if (idx >= BATCH * DM * NCH) return;
    int d = idx % DM;
    int rest = idx / DM;
    int ch = rest % NCH;
    int b = rest / NCH;
    int CL = (L + NCH - 1) / NCH;
    int t0 = ch * CL;
    int t1 = t0 + CL < L ? t0 + CL : L;
    if (t0 >= L) return;
    const float* base = S + (size_t)b * L * DM + d;
    float s = 0.f;
#pragma unroll
    for (int u = -KHALF; u <= KHALF; u++) {
        int tt = t0 + u; tt = tt < 0 ? 0 : (tt >= L ? L - 1 : tt);
        s += base[(size_t)tt * DM];
    }
    for (int t = t0; t < t1; t++) {
        float m = s * (1.f / KSZ);
        size_t o = ((size_t)(b * L + t)) * DM + d;
        seas[o] = base[(size_t)t * DM] - m;
        if (mode == 1) trend[o] = m;
        else if (mode == 2) trend[o] += m;
        int rm = t - KHALF; rm = rm < 0 ? 0 : rm;
        int ad = t + KHALF + 1; ad = ad >= L ? L - 1 : ad;
        s += base[(size_t)ad * DM] - base[(size_t)rm * DM];
    }
}

__global__ void __launch_bounds__(256) k_topk(const float* __restrict__ mc,
                                              float* __restrict__ w, int* __restrict__ dly,
                                              int L, int K) {
    __shared__ float vals[LDEC];
    __shared__ float rv[256];
    __shared__ int ri[256];
    __shared__ float selv[32];
    __shared__ int seli[32];
    int b = blockIdx.x, tid = threadIdx.x;
    for (int j = tid; j < L; j += 256) vals[j] = mc[b * L + j];
    __syncthreads();
    for (int it = 0; it < K; it++) {
        float best = -1e30f; int bi = 0;
        for (int j = tid; j < L; j += 256) {
            float v = vals[j];
            if (v > best) { best = v; bi = j; }
        }
        rv[tid] = best; ri[tid] = bi;
        __syncthreads();
        for (int s = 128; s > 0; s >>= 1) {
            if (tid < s) {
                if (rv[tid + s] > rv[tid] ||
                    (rv[tid + s] == rv[tid] && ri[tid + s] < ri[tid])) {
                    rv[tid] = rv[tid + s]; ri[tid] = ri[tid + s];
                }
            }
            __syncthreads();
        }
        if (tid == 0) { selv[it] = rv[0]; seli[it] = ri[0]; vals[ri[0]] = -1e30f; }
        __syncthreads();
    }
    if (tid == 0) {
        float mx = selv[0], ssum = 0.f;
        for (int i = 0; i < K; i++) { float e = expf(selv[i] - mx); selv[i] = e; ssum += e; }
        for (int i = 0; i < K; i++) { w[b * 32 + i] = selv[i] / ssum; dly[b * 32 + i] = seli[i]; }
    }
}

__global__ void __launch_bounds__(128) k_agg(
    const float* __restrict__ v, const float* __restrict__ w,
    const int* __restrict__ dly, float* __restrict__ out, int L, int K) {
    __shared__ float ws[32];
    __shared__ int ds[32];
    int blk = blockIdx.x;
    int b = blk / L, t = blk % L;
    int d4 = threadIdx.x;
    if (d4 < K) { ws[d4] = w[b * 32 + d4]; ds[d4] = dly[b * 32 + d4]; }
    __syncthreads();
    float4 s = make_float4(0.f, 0.f, 0.f, 0.f);
    for (int i = 0; i < K; i++) {
        int tt = t + ds[i]; if (tt >= L) tt -= L;
        float4 vv = *(const float4*)&v[((size_t)(b * L + tt)) * DM + d4 * 4];
        float wi = ws[i];
        s.x += wi * vv.x; s.y += wi * vv.y; s.z += wi * vv.z; s.w += wi * vv.w;
    }
    *(float4*)&out[((size_t)(b * L + t)) * DM + d4 * 4] = s;
}

__global__ void __launch_bounds__(128) k_ln(const float* __restrict__ X,
                                            const float* __restrict__ g,
                                            const float* __restrict__ be,
                                            float* __restrict__ Y) {
    __shared__ float red[4];
    int row = blockIdx.x, tid = threadIdx.x;
    int lane = tid & 31, warp = tid >> 5;
    float4 xv = *(const float4*)&X[(size_t)row * DM + tid * 4];

    float s = xv.x + xv.y + xv.z + xv.w;
#pragma unroll
    for (int o = 16; o > 0; o >>= 1) s += __shfl_down_sync(0xffffffffu, s, o);
    if (lane == 0) red[warp] = s;
    __syncthreads();
    float mu = (red[0] + red[1] + red[2] + red[3]) * (1.f / DM);
    __syncthreads();

    float4 dv = make_float4(xv.x - mu, xv.y - mu, xv.z - mu, xv.w - mu);
    float v = dv.x * dv.x + dv.y * dv.y + dv.z * dv.z + dv.w * dv.w;
#pragma unroll
    for (int o = 16; o > 0; o >>= 1) v += __shfl_down_sync(0xffffffffu, v, o);
    if (lane == 0) red[warp] = v;
    __syncthreads();
    float inv = rsqrtf((red[0] + red[1] + red[2] + red[3]) * (1.f / DM) + 1e-5f);

    float4 gv = *(const float4*)&g[tid * 4];
    float4 bv = *(const float4*)&be[tid * 4];
    float4 yv = make_float4(dv.x * inv * gv.x + bv.x, dv.y * inv * gv.y + bv.y,
                            dv.z * inv * gv.z + bv.z, dv.w * inv * gv.w + bv.w);
    *(float4*)&Y[(size_t)row * DM + tid * 4] = yv;
}

__global__ void __launch_bounds__(128) k_colsum(const float* __restrict__ Y,
                                                float* __restrict__ cm, int L) {
    int b = blockIdx.x, chunk = blockIdx.y, nch = gridDim.y;
    int d4 = threadIdx.x;
    float4 s = make_float4(0.f, 0.f, 0.f, 0.f);
    for (int t = chunk; t < L; t += nch) {
        float4 y = *(const float4*)&Y[((size_t)(b * L + t)) * DM + d4 * 4];
        s.x += y.x; s.y += y.y; s.z += y.z; s.w += y.w;
    }
    atomicAdd(&cm[b * DM + d4 * 4 + 0], s.x);
    atomicAdd(&cm[b * DM + d4 * 4 + 1], s.y);
    atomicAdd(&cm[b * DM + d4 * 4 + 2], s.z);
    atomicAdd(&cm[b * DM + d4 * 4 + 3], s.w);
}

__global__ void k_subcm(float* __restrict__ Y, const float* __restrict__ cm, int L) {
    size_t i4 = (size_t)blockIdx.x * blockDim.x + threadIdx.x;
    size_t total4 = (size_t)BATCH * L * DM / 4;
    if (i4 >= total4) return;
    int d4 = (int)(i4 % (DM / 4));
    int b = (int)(i4 / ((size_t)L * (DM / 4)));
    float4 y = *(float4*)&Y[i4 * 4];
    float4 c = *(const float4*)&cm[b * DM + d4 * 4];
    float invL = 1.f / (float)L;
    y.x -= c.x * invL; y.y -= c.y * invL; y.z -= c.z * invL; y.w -= c.w * invL;
    *(float4*)&Y[i4 * 4] = y;
}

__global__ void __launch_bounds__(224) k_final(const float* __restrict__ xh,
                                               const float* __restrict__ tsum,
                                               const float* __restrict__ tdec,
                                               const float* __restrict__ Wtr,
                                               const float* __restrict__ Wp,
                                               const float* __restrict__ bp,
                                               float* __restrict__ out) {
    __shared__ float xs[DM];
    __shared__ float ts[3][DM];
    int blk = blockIdx.x;
    int b = blk / PRED, to = blk % PRED;
    int t = to + LABEL;
    int tid = threadIdx.x;
    for (int d = tid; d < DM; d += 224) xs[d] = xh[((size_t)(b * LDEC + t)) * DM + d];
    for (int w = 0; w < 3; w++) {
        int tt = (t - 1 + w + LDEC) % LDEC;
        for (int d = tid; d < DM; d += 224) ts[w][d] = tsum[((size_t)(b * LDEC + tt)) * DM + d];
    }
    __syncthreads();
    int c = tid >> 5, lane = tid & 31;
    float s = 0.f;
    for (int d = lane; d < DM; d += 32) {
        s += xs[d] * Wp[d * CC + c];
        s += ts[0][d] * Wtr[(0 * DM + d) * CC + c];
        s += ts[1][d] * Wtr[(1 * DM + d) * CC + c];
        s += ts[2][d] * Wtr[(2 * DM + d) * CC + c];
    }
    for (int o = 16; o > 0; o >>= 1) s += __shfl_down_sync(0xffffffffu, s, o);
    if (lane == 0)
        out[(b * PRED + to) * CC + c] = s + bp[c] + tdec[(b * LDEC + t) * CC + c];
}

// ---------------- host orchestration ----------------
extern "C" void kernel_launch(void* const* d_in, const int* in_sizes, int n_in,
                              void* d_out, int out_size) {
    const float* x_enc      = (const float*)d_in[0];
    const float* x_mark_enc = (const float*)d_in[1];
    const float* x_mark_dec = (const float*)d_in[3];
    const float* W_enc_emb  = (const float*)d_in[4];
    const float* W_mark_enc = (const float*)d_in[5];
    const float* W_dec_emb  = (const float*)d_in[6];
    const float* W_mark_dec = (const float*)d_in[7];
    const float* eW_attn    = (const float*)d_in[8];
    const float* eb_attn    = (const float*)d_in[9];
    const float* eW1        = (const float*)d_in[10];
    const float* eW2        = (const float*)d_in[11];
    const float* eg         = (const float*)d_in[12];
    const float* ebeta      = (const float*)d_in[13];
    const float* sW         = (const float*)d_in[14];
    const float* sb         = (const float*)d_in[15];
    const float* cW         = (const float*)d_in[16];
    const float* cb         = (const float*)d_in[17];
    const float* dW1        = (const float*)d_in[18];
    const float* dW2        = (const float*)d_in[19];
    const float* W_trend    = (const float*)d_in[20];
    const float* dg         = (const float*)d_in[21];
    const float* dbeta      = (const float*)d_in[22];
    const float* Wproj      = (const float*)d_in[23];
    const float* bproj      = (const float*)d_in[24];
    float* out = (float*)d_out;

    void* p;
    float *x, *sum, *q, *k, *v, *agg, *enc, *ffn, *tsum, *mc, *wts, *cm, *m7, *s7, *t7, *sdec, *tdec, *mdec;
    int* dly;
    cudaGetSymbolAddress(&p, g_x);    x    = (float*)p;
    cudaGetSymbolAddress(&p, g_sum);  sum  = (float*)p;
    cudaGetSymbolAddress(&p, g_q);    q    = (float*)p;
    cudaGetSymbolAddress(&p, g_k);    k    = (float*)p;
    cudaGetSymbolAddress(&p, g_v);    v    = (float*)p;
    cudaGetSymbolAddress(&p, g_agg);  agg  = (float*)p;
    cudaGetSymbolAddress(&p, g_enc);  enc  = (float*)p;
    cudaGetSymbolAddress(&p, g_ffn);  ffn  = (float*)p;
    cudaGetSymbolAddress(&p, g_tsum); tsum = (float*)p;
    cudaGetSymbolAddress(&p, g_mc);   mc   = (float*)p;
    cudaGetSymbolAddress(&p, g_wts);  wts  = (float*)p;
    cudaGetSymbolAddress(&p, g_dly);  dly  = (int*)p;
    cudaGetSymbolAddress(&p, g_cm);   cm   = (float*)p;
    cudaGetSymbolAddress(&p, g_m7);   m7   = (float*)p;
    cudaGetSymbolAddress(&p, g_s7);   s7   = (float*)p;
    cudaGetSymbolAddress(&p, g_t7);   t7   = (float*)p;
    cudaGetSymbolAddress(&p, g_sdec); sdec = (float*)p;
    cudaGetSymbolAddress(&p, g_tdec); tdec = (float*)p;
    cudaGetSymbolAddress(&p, g_mdec); mdec = (float*)p;

    const int rowsE = BATCH * LE;     // 16384
    const int rowsD = BATCH * LDEC;   // 18944 = 148*128
    const int KE = (int)(3.0 * log(512.0));  // 18
    const int KD = (int)(3.0 * log(592.0));  // 19

    auto GN = [](int M, int N) { return dim3((unsigned)((N + 127) / 128), (unsigned)((M + 127) / 128), 1); };
    auto GT = [](int M, int N) { return dim3((unsigned)(N / 128), (unsigned)(M / 128), 1); };

    // ---- series_decomp of x_enc + decoder inits ----
    k_mean7<<<(BATCH * CC * 32 + 255) / 256, 256>>>(x_enc, m7);
    {
        int n = BATCH * LE * CC;
        k_decomp7<<<(n + 255) / 256, 256>>>(x_enc, s7, t7);
    }
    {
        int n = BATCH * LDEC * CC;
        k_build_dec<<<(n + 255) / 256, 256>>>(s7, t7, m7, sdec, tdec);
        int nm = BATCH * LDEC * MMK;
        k_build_mark<<<(nm + 255) / 256, 256>>>(x_mark_enc, x_mark_dec, mdec);
    }

    // ---- attention helper: writes outBuf = resBuf + attn_out ----
    auto attn = [&](const float* qin, const float* kin, const float* vin,
                    int rowsQ, int rowsKV, int L, int Lk, int Kk,
                    const float* W, const float* bb, bool kvPad,
                    const float* resBuf, float* outBuf) {
        mma_gemm<<<GT(rowsQ, DM), 256>>>(qin, W, bb, nullptr, q, rowsQ, DM, DM, 0);
        if (kvPad) {
            int nPad4 = BATCH * (LDEC - LE) * (DM / 4);
            k_zero_pad<<<(nPad4 + 255) / 256, 256>>>(k, LE, LDEC);
            k_zero_pad<<<(nPad4 + 255) / 256, 256>>>(v, LE, LDEC);
            gemm_nn<<<GN(rowsKV, DM), 256>>>(kin, W + DM * DM, bb + DM, nullptr, k, rowsKV, DM, DM, LE, LDEC, 0);
            gemm_nn<<<GN(rowsKV, DM), 256>>>(vin, W + 2 * DM * DM, bb + 2 * DM, nullptr, v, rowsKV, DM, DM, LE, LDEC, 0);
        } else {
            mma_gemm<<<GT(rowsKV, DM), 256>>>(kin, W + DM * DM, bb + DM, nullptr, k, rowsKV, DM, DM, 0);
            mma_gemm<<<GT(rowsKV, DM), 256>>>(vin, W + 2 * DM * DM, bb + 2 * DM, nullptr, v, rowsKV, DM, DM, 0);
        }
        int n = BATCH * L;
        k_zero<<<(n + 255) / 256, 256>>>(mc, n);
        gemm_nt_fold<<<dim3((unsigned)((Lk + 127) / 128), (unsigned)((L + 127) / 128), BATCH), 256>>>(q, k, mc, L, Lk, DM);
        k_topk<<<BATCH, 256>>>(mc, wts, dly, L, Kk);
        k_agg<<<BATCH * L, 128>>>(v, wts, dly, agg, L, Kk);
        mma_gemm<<<GT(rowsQ, DM), 256>>>(agg, W + 3 * DM * DM, bb + 3 * DM, resBuf, outBuf, rowsQ, DM, DM, 0);
    };

    const int nSW = BATCH * DM * NCH;

    // ================= encoder =================
    k_embed<<<BATCH * (LE / 8), 512>>>(x_enc, x_mark_enc, W_enc_emb, W_mark_enc, x, LE);

    for (int l = 0; l < 2; l++) {
        const float* W  = eW_attn + (size_t)l * 4 * DM * DM;
        const float* bb = eb_attn + (size_t)l * 4 * DM;
        attn(x, x, x, rowsE, rowsE, LE, LE, KE, W, bb, false, x, sum);   // sum = x + attn(x)
        k_decomp_sw<<<(nSW + 255) / 256, 256>>>(sum, x, tsum, LE, 0);
        mma_gemm<<<GT(rowsE, DFF), 256>>>(x, eW1 + (size_t)l * DM * DFF, nullptr, nullptr, ffn, rowsE, DFF, DM, 1);
        mma_gemm<<<GT(rowsE, DM), 256>>>(ffn, eW2 + (size_t)l * DFF * DM, nullptr, x, sum, rowsE, DM, DFF, 0);
        k_decomp_sw<<<(nSW + 255) / 256, 256>>>(sum, x, tsum, LE, 0);
    }
    // enc_out = my_layernorm(x, eg, ebeta)
    k_ln<<<rowsE, 128>>>(x, eg, ebeta, enc);
    {
        int n = BATCH * DM;
        k_zero<<<(n + 255) / 256, 256>>>(cm, n);
        k_colsum<<<dim3(BATCH, 8), 128>>>(enc, cm, LE);
        int n4 = rowsE * DM / 4;
        k_subcm<<<(n4 + 255) / 256, 256>>>(enc, cm, LE);
    }

    // ================= decoder =================
    k_embed<<<BATCH * (LDEC / 8), 512>>>(sdec, mdec, W_dec_emb, W_mark_dec, x, LDEC);

    // self attention
    attn(x, x, x, rowsD, rowsD, LDEC, LDEC, KD, sW, sb, false, x, sum);
    k_decomp_sw<<<(nSW + 255) / 256, 256>>>(sum, x, tsum, LDEC, 1);   // write t1

    // cross attention (K/V from encoder output, zero-padded 512->592)
    attn(x, enc, enc, rowsD, rowsE, LDEC, LE, KD, cW, cb, true, x, sum);
    k_decomp_sw<<<(nSW + 255) / 256, 256>>>(sum, x, tsum, LDEC, 2);   // += t2

    // FFN
    mma_gemm<<<GT(rowsD, DFF), 256>>>(x, dW1, nullptr, nullptr, ffn, rowsD, DFF, DM, 1);
    mma_gemm<<<GT(rowsD, DM), 256>>>(ffn, dW2, nullptr, x, sum, rowsD, DM, DFF, 0);
    k_decomp_sw<<<(nSW + 255) / 256, 256>>>(sum, x, tsum, LDEC, 2);   // += t3

    // my_layernorm(x, dg, dbeta) -> sum (reused as xh buffer)
    k_ln<<<rowsD, 128>>>(x, dg, dbeta, sum);
    {
        int n = BATCH * DM;
        k_zero<<<(n + 255) / 256, 256>>>(cm, n);
        k_colsum<<<dim3(BATCH, 8), 128>>>(sum, cm, LDEC);
        int n4 = rowsD * DM / 4;
        k_subcm<<<(n4 + 255) / 256, 256>>>(sum, cm, LDEC);
    }

    // final: seasonal projection + trend conv + slice
    k_final<<<BATCH * PRED, 224>>>(sum, tsum, tdec, W_trend, Wproj, bproj, out);
}

// round 14
// speedup vs baseline: 1.7154x; 1.0922x over previous
#include <cuda_runtime.h>
#include <cuda_bf16.h>
#include <math.h>
#include <stdint.h>

// ---------------- problem constants ----------------
#define BATCH 32
#define DM    512
#define DFF   2048
#define LE    512      // encoder length
#define LDEC  592      // decoder length (label 256 + pred 336)
#define CC    7
#define MMK   4
#define LABEL 256
#define PRED  336
#define KSZ   25
#define KHALF 12
#define NCH   8        // time chunks for sliding-window decomp

// ---------------- device scratch (static, no allocation) ----------------
__device__ float g_x   [BATCH*LDEC*DM];
__device__ float g_sum [BATCH*LDEC*DM];
__device__ float g_q   [BATCH*LDEC*DM];
__device__ float g_k   [BATCH*LDEC*DM];
__device__ float g_v   [BATCH*LDEC*DM];
__device__ float g_agg [BATCH*LDEC*DM];
__device__ float g_enc [BATCH*LE*DM];
__device__ float g_ffn [BATCH*LDEC*DFF];
__device__ float g_tsum[BATCH*LDEC*DM];
__device__ float g_mc  [BATCH*LDEC];
__device__ float g_wts [BATCH*32];
__device__ int   g_dly [BATCH*32];
__device__ float g_cm  [BATCH*DM];
__device__ float g_m7  [BATCH*CC];
__device__ float g_s7  [BATCH*LE*CC];
__device__ float g_t7  [BATCH*LE*CC];
__device__ float g_sdec[BATCH*LDEC*CC];
__device__ float g_tdec[BATCH*LDEC*CC];
__device__ float g_mdec[BATCH*LDEC*MMK];

// ================= mma.sync split-bf16 helpers (baseline ISA, sm_80+) =======
__device__ __forceinline__ void mma_bf16(float& d0, float& d1, float& d2, float& d3,
                                         uint32_t a0, uint32_t a1, uint32_t a2, uint32_t a3,
                                         uint32_t b0, uint32_t b1) {
    asm volatile(
        "mma.sync.aligned.m16n8k16.row.col.f32.bf16.bf16.f32 "
        "{%0,%1,%2,%3}, {%4,%5,%6,%7}, {%8,%9}, {%0,%1,%2,%3};"
        : "+f"(d0), "+f"(d1), "+f"(d2), "+f"(d3)
        : "r"(a0), "r"(a1), "r"(a2), "r"(a3), "r"(b0), "r"(b1));
}

__device__ __forceinline__ void split_pack(float x0, float x1,
                                           uint32_t& hi, uint32_t& lo) {
    __nv_bfloat16 h0 = __float2bfloat16(x0), h1 = __float2bfloat16(x1);
    float l0 = x0 - __bfloat162float(h0), l1 = x1 - __bfloat162float(h1);
    __nv_bfloat162 hp; hp.x = h0; hp.y = h1;
    __nv_bfloat162 lp; lp.x = __float2bfloat16(l0); lp.y = __float2bfloat16(l1);
    hi = *(uint32_t*)&hp;
    lo = *(uint32_t*)&lp;
}

// ================= split-bf16 NN GEMM =======================================
// C[M,N] = A[M,K] @ B[K,N] (+bias)(+res)(+gelu), fp32 in/out.
// D += Ah*Bh + Ah*Bl + Al*Bh (fp32 acc). 128x128 tile, BK=32, 8 warps (2x4),
// warp tile 64x32 = 4x4 frags of m16n8k16. SMEM row stride 40 bf16.
// rpbIn/rpbOut: optional output-row remap (epilogue only; tiles never straddle
// a rpbIn-row group since rpbIn % 128 == 0 in all uses).
// REQUIRES M % 128 == 0, N % 128 == 0, K % 32 == 0.
#define PADK 40

__global__ void __launch_bounds__(256) mma_gemm(
    const float* __restrict__ A, const float* __restrict__ B,
    const float* __restrict__ bias, const float* __restrict__ res,
    float* __restrict__ C, int M, int N, int K,
    int rpbIn, int rpbOut, int gelu)
{
    __shared__ __align__(16) __nv_bfloat16 aHi[128 * PADK];
    __shared__ __align__(16) __nv_bfloat16 aLo[128 * PADK];
    __shared__ __align__(16) __nv_bfloat16 bHi[128 * PADK];
    __shared__ __align__(16) __nv_bfloat16 bLo[128 * PADK];
    uint32_t* uaHi = (uint32_t*)aHi;
    uint32_t* uaLo = (uint32_t*)aLo;
    uint32_t* ubHi = (uint32_t*)bHi;
    uint32_t* ubLo = (uint32_t*)bLo;

    int tid = threadIdx.x;
    int warp = tid >> 5, lane = tid & 31;
    int mw = warp >> 2, nw = warp & 3;
    int g = lane >> 2, tig = lane & 3;
    int m0 = blockIdx.y * 128, n0 = blockIdx.x * 128;

    float acc[4][4][4];
#pragma unroll
    for (int m = 0; m < 4; m++)
#pragma unroll
        for (int n = 0; n < 4; n++)
#pragma unroll
            for (int i = 0; i < 4; i++) acc[m][n][i] = 0.f;

    int arow = tid >> 1, ahalf = tid & 1;
    int bnn = tid >> 1, bhalf = tid & 1;

    for (int k0 = 0; k0 < K; k0 += 32) {
        {
            const float* src = A + (size_t)(m0 + arow) * K + k0 + ahalf * 16;
            float4 f0 = *(const float4*)(src);
            float4 f1 = *(const float4*)(src + 4);
            float4 f2 = *(const float4*)(src + 8);
            float4 f3 = *(const float4*)(src + 12);
            float xs[16] = {f0.x, f0.y, f0.z, f0.w, f1.x, f1.y, f1.z, f1.w,
                            f2.x, f2.y, f2.z, f2.w, f3.x, f3.y, f3.z, f3.w};
            int base = arow * 20 + ahalf * 8;
#pragma unroll
            for (int j = 0; j < 8; j++) {
                uint32_t hw, lw;
                split_pack(xs[2 * j], xs[2 * j + 1], hw, lw);
                uaHi[base + j] = hw;
                uaLo[base + j] = lw;
            }
        }
        {
            float xs[16];
#pragma unroll
            for (int j = 0; j < 16; j++)
                xs[j] = B[(size_t)(k0 + bhalf * 16 + j) * N + n0 + bnn];
            int base = bnn * 20 + bhalf * 8;
#pragma unroll
            for (int j = 0; j < 8; j++) {
                uint32_t hw, lw;
                split_pack(xs[2 * j], xs[2 * j + 1], hw, lw);
                ubHi[base + j] = hw;
                ubLo[base + j] = lw;
            }
        }
        __syncthreads();

#pragma unroll
        for (int s = 0; s < 2; s++) {
            int ko = 8 * s + tig;
            uint32_t Bh[4][2], Bl[4][2];
#pragma unroll
            for (int n = 0; n < 4; n++) {
                int cb = (nw * 32 + n * 8 + g) * 20 + ko;
                Bh[n][0] = ubHi[cb];     Bh[n][1] = ubHi[cb + 4];
                Bl[n][0] = ubLo[cb];     Bl[n][1] = ubLo[cb + 4];
            }
#pragma unroll
            for (int m = 0; m < 4; m++) {
                int r0 = (mw * 64 + m * 16 + g) * 20 + ko;
                int r1 = r0 + 8 * 20;
                uint32_t Ah0 = uaHi[r0], Ah1 = uaHi[r1];
                uint32_t Ah2 = uaHi[r0 + 4], Ah3 = uaHi[r1 + 4];
                uint32_t Al0 = uaLo[r0], Al1 = uaLo[r1];
                uint32_t Al2 = uaLo[r0 + 4], Al3 = uaLo[r1 + 4];
#pragma unroll
                for (int n = 0; n < 4; n++) {
                    mma_bf16(acc[m][n][0], acc[m][n][1], acc[m][n][2], acc[m][n][3],
                             Ah0, Ah1, Ah2, Ah3, Bh[n][0], Bh[n][1]);
                    mma_bf16(acc[m][n][0], acc[m][n][1], acc[m][n][2], acc[m][n][3],
                             Ah0, Ah1, Ah2, Ah3, Bl[n][0], Bl[n][1]);
                    mma_bf16(acc[m][n][0], acc[m][n][1], acc[m][n][2], acc[m][n][3],
                             Al0, Al1, Al2, Al3, Bh[n][0], Bh[n][1]);
                }
            }
        }
        __syncthreads();
    }

#pragma unroll
    for (int m = 0; m < 4; m++) {
        int gr0 = m0 + mw * 64 + m * 16 + g;
        int gr1 = gr0 + 8;
        int row0 = gr0, row1 = gr1;
        if (rpbIn != rpbOut) {
            row0 = (gr0 / rpbIn) * rpbOut + (gr0 % rpbIn);
            row1 = (gr1 / rpbIn) * rpbOut + (gr1 % rpbIn);
        }
#pragma unroll
        for (int n = 0; n < 4; n++) {
            int col = n0 + nw * 32 + n * 8 + 2 * tig;
            float v0 = acc[m][n][0], v1 = acc[m][n][1];
            float v2 = acc[m][n][2], v3 = acc[m][n][3];
            if (bias) {
                float2 bb = *(const float2*)&bias[col];
                v0 += bb.x; v1 += bb.y; v2 += bb.x; v3 += bb.y;
            }
            if (res) {
                float2 r0 = *(const float2*)&res[(size_t)row0 * N + col];
                float2 r1 = *(const float2*)&res[(size_t)row1 * N + col];
                v0 += r0.x; v1 += r0.y; v2 += r1.x; v3 += r1.y;
            }
            if (gelu) {
                v0 *= normcdff(v0); v1 *= normcdff(v1);
                v2 *= normcdff(v2); v3 *= normcdff(v3);
            }
            *(float2*)&C[(size_t)row0 * N + col] = make_float2(v0, v1);
            *(float2*)&C[(size_t)row1 * N + col] = make_float2(v2, v3);
        }
    }
}

// ================= split-bf16 NT GEMM + diagonal fold =======================
// S[b,i,j] = sum_d Q[b,i,d]*K[b,j,d] computed tile-locally via HMMA, folded to
// mc[b,tau] += (1/DM)*sum_{(i-j) mod L == tau} S[i,j] without materializing S.
// Both operands K-contiguous -> identical coalesced staging for A and B.
// Boundary rows (>= L / >= Lk) staged as zeros: zero contribution to fold.
// mc must be pre-zeroed.
__global__ void __launch_bounds__(256) mma_nt_fold(
    const float* __restrict__ Q, const float* __restrict__ Km,
    float* __restrict__ mc, int L, int Lk, int D)
{
    __shared__ __align__(16) __nv_bfloat16 aHi[128 * PADK];
    __shared__ __align__(16) __nv_bfloat16 aLo[128 * PADK];
    __shared__ __align__(16) __nv_bfloat16 bHi[128 * PADK];
    __shared__ __align__(16) __nv_bfloat16 bLo[128 * PADK];
    __shared__ float bins[255];
    uint32_t* uaHi = (uint32_t*)aHi;
    uint32_t* uaLo = (uint32_t*)aLo;
    uint32_t* ubHi = (uint32_t*)bHi;
    uint32_t* ubLo = (uint32_t*)bLo;

    int b = blockIdx.z;
    const float* Ab = Q  + (size_t)b * L * D;
    const float* Bb = Km + (size_t)b * L * D;
    int tid = threadIdx.x;
    int warp = tid >> 5, lane = tid & 31;
    int mw = warp >> 2, nw = warp & 3;
    int g = lane >> 2, tig = lane & 3;
    int m0 = blockIdx.y * 128, n0 = blockIdx.x * 128;

    float acc[4][4][4];
#pragma unroll
    for (int m = 0; m < 4; m++)
#pragma unroll
        for (int n = 0; n < 4; n++)
#pragma unroll
            for (int i = 0; i < 4; i++) acc[m][n][i] = 0.f;

    int lrow = tid >> 1, half = tid & 1;
    bool aok = (m0 + lrow) < L;
    bool bok = (n0 + lrow) < Lk;

    for (int k0 = 0; k0 < D; k0 += 32) {
        // A rows (Q)
        {
            float xs[16];
            if (aok) {
                const float* src = Ab + (size_t)(m0 + lrow) * D + k0 + half * 16;
                float4 f0 = *(const float4*)(src);
                float4 f1 = *(const float4*)(src + 4);
                float4 f2 = *(const float4*)(src + 8);
                float4 f3 = *(const float4*)(src + 12);
                xs[0]=f0.x; xs[1]=f0.y; xs[2]=f0.z; xs[3]=f0.w;
                xs[4]=f1.x; xs[5]=f1.y; xs[6]=f1.z; xs[7]=f1.w;
                xs[8]=f2.x; xs[9]=f2.y; xs[10]=f2.z; xs[11]=f2.w;
                xs[12]=f3.x; xs[13]=f3.y; xs[14]=f3.z; xs[15]=f3.w;
            } else {
#pragma unroll
                for (int j = 0; j < 16; j++) xs[j] = 0.f;
            }
            int base = lrow * 20 + half * 8;
#pragma unroll
            for (int j = 0; j < 8; j++) {
                uint32_t hw, lw;
                split_pack(xs[2 * j], xs[2 * j + 1], hw, lw);
                uaHi[base + j] = hw;
                uaLo[base + j] = lw;
            }
        }
        // B rows (K) -- same layout, no transpose
        {
            float xs[16];
            if (bok) {
                const float* src = Bb + (size_t)(n0 + lrow) * D + k0 + half * 16;
                float4 f0 = *(const float4*)(src);
                float4 f1 = *(const float4*)(src + 4);
                float4 f2 = *(const float4*)(src + 8);
                float4 f3 = *(const float4*)(src + 12);
                xs[0]=f0.x; xs[1]=f0.y; xs[2]=f0.z; xs[3]=f0.w;
                xs[4]=f1.x; xs[5]=f1.y; xs[6]=f1.z; xs[7]=f1.w;
                xs[8]=f2.x; xs[9]=f2.y; xs[10]=f2.z; xs[11]=f2.w;
                xs[12]=f3.x; xs[13]=f3.y; xs[14]=f3.z; xs[15]=f3.w;
            } else {
#pragma unroll
                for (int j = 0; j < 16; j++) xs[j] = 0.f;
            }
            int base = lrow * 20 + half * 8;
#pragma unroll
            for (int j = 0; j < 8; j++) {
                uint32_t hw, lw;
                split_pack(xs[2 * j], xs[2 * j + 1], hw, lw);
                ubHi[base + j] = hw;
                ubLo[base + j] = lw;
            }
        }
        __syncthreads();

#pragma unroll
        for (int s = 0; s < 2; s++) {
            int ko = 8 * s + tig;
            uint32_t Bh[4][2], Bl[4][2];
#pragma unroll
            for (int n = 0; n < 4; n++) {
                int cb = (nw * 32 + n * 8 + g) * 20 + ko;
                Bh[n][0] = ubHi[cb];     Bh[n][1] = ubHi[cb + 4];
                Bl[n][0] = ubLo[cb];     Bl[n][1] = ubLo[cb + 4];
            }
#pragma unroll
            for (int m = 0; m < 4; m++) {
                int r0 = (mw * 64 + m * 16 + g) * 20 + ko;
                int r1 = r0 + 8 * 20;
                uint32_t Ah0 = uaHi[r0], Ah1 = uaHi[r1];
                uint32_t Ah2 = uaHi[r0 + 4], Ah3 = uaHi[r1 + 4];
                uint32_t Al0 = uaLo[r0], Al1 = uaLo[r1];
                uint32_t Al2 = uaLo[r0 + 4], Al3 = uaLo[r1 + 4];
#pragma unroll
                for (int n = 0; n < 4; n++) {
                    mma_bf16(acc[m][n][0], acc[m][n][1], acc[m][n][2], acc[m][n][3],
                             Ah0, Ah1, Ah2, Ah3, Bh[n][0], Bh[n][1]);
                    mma_bf16(acc[m][n][0], acc[m][n][1], acc[m][n][2], acc[m][n][3],
                             Ah0, Ah1, Ah2, Ah3, Bl[n][0], Bl[n][1]);
                    mma_bf16(acc[m][n][0], acc[m][n][1], acc[m][n][2], acc[m][n][3],
                             Al0, Al1, Al2, Al3, Bh[n][0], Bh[n][1]);
                }
            }
        }
        __syncthreads();
    }

    // ---- fold: register pre-reduction over 22 distinct taus ----
    // fragment (m, n, ci): lm = mw*64 + m*16 + g + 8*r1, ln = nw*32 + n*8 + 2*tig + r2
    // tau_local = 8*((2m + r1) - n) - r2; index c = (2m+r1)-n in [-3, 7]
    for (int i = tid; i < 255; i += 256) bins[i] = 0.f;
    __syncthreads();
    {
        float tb[11][2];
#pragma unroll
        for (int i = 0; i < 11; i++) { tb[i][0] = 0.f; tb[i][1] = 0.f; }
#pragma unroll
        for (int m = 0; m < 4; m++)
#pragma unroll
            for (int n = 0; n < 4; n++) {
                tb[2 * m - n + 3][0]     += acc[m][n][0];   // r1=0, r2=0
                tb[2 * m - n + 3][1]     += acc[m][n][1];   // r1=0, r2=1
                tb[2 * m + 1 - n + 3][0] += acc[m][n][2];   // r1=1, r2=0
                tb[2 * m + 1 - n + 3][1] += acc[m][n][3];   // r1=1, r2=1
            }
        int baseTau = (mw * 64 + g) - (nw * 32 + 2 * tig) + 127;
#pragma unroll
        for (int c = -3; c <= 7; c++) {
#pragma unroll
            for (int r2 = 0; r2 < 2; r2++) {
                float v = tb[c + 3][r2];
                if (v != 0.f) atomicAdd(&bins[baseTau + 8 * c - r2], v);
            }
        }
    }
    __syncthreads();
    int base = m0 - n0;
    for (int i = tid; i < 255; i += 256) {
        float vbin = bins[i];
        if (vbin != 0.f) {
            int tau = base + i - 127;
            tau %= L; if (tau < 0) tau += L;
            atomicAdd(&mc[b * L + tau], vbin * (1.f / DM));
        }
    }
}

// ---------------- small kernels ----------------
__global__ void __launch_bounds__(256) k_mean7(const float* __restrict__ x,
                                               float* __restrict__ m7) {
    int wid = (blockIdx.x * blockDim.x + threadIdx.x) >> 5;
    int lane = threadIdx.x & 31;
    if (wid >= BATCH * CC) return;
    int b = wid / CC, c = wid % CC;
    float s = 0.f;
    for (int i = lane; i < LE; i += 32) s += x[(b * LE + i) * CC + c];
#pragma unroll
    for (int o = 16; o > 0; o >>= 1) s += __shfl_down_sync(0xffffffffu, s, o);
    if (lane == 0) m7[wid] = s / LE;
}

__global__ void k_decomp7(const float* __restrict__ x, float* __restrict__ seas,
                          float* __restrict__ tr) {
    int idx = blockIdx.x * blockDim.x + threadIdx.x;
    if (idx >= BATCH * LE * CC) return;
    int c = idx % CC, t = (idx / CC) % LE, b = idx / (CC * LE);
    float s = 0.f;
#pragma unroll
    for (int u = -KHALF; u <= KHALF; u++) {
        int tt = t + u; tt = tt < 0 ? 0 : (tt >= LE ? LE - 1 : tt);
        s += x[(b * LE + tt) * CC + c];
    }
    float m = s * (1.f / KSZ);
    seas[idx] = x[idx] - m;
    tr[idx] = m;
}

__global__ void k_build_dec(const float* __restrict__ s7, const float* __restrict__ t7,
                            const float* __restrict__ m7, float* __restrict__ sdec,
                            float* __restrict__ tdec) {
    int idx = blockIdx.x * blockDim.x + threadIdx.x;
    if (idx >= BATCH * LDEC * CC) return;
    int c = idx % CC, t = (idx / CC) % LDEC, b = idx / (CC * LDEC);
    if (t < LABEL) {
        int src = (b * LE + (LE - LABEL) + t) * CC + c;
        sdec[idx] = s7[src];
        tdec[idx] = t7[src];
    } else {
        sdec[idx] = 0.f;
        tdec[idx] = m7[b * CC + c];
    }
}

__global__ void k_build_mark(const float* __restrict__ me, const float* __restrict__ md,
                             float* __restrict__ out) {
    int idx = blockIdx.x * blockDim.x + threadIdx.x;
    if (idx >= BATCH * LDEC * MMK) return;
    int m = idx % MMK, t = (idx / MMK) % LDEC, b = idx / (MMK * LDEC);
    out[idx] = (t < LABEL) ? me[(b * LE + (LE - LABEL) + t) * MMK + m]
                           : md[(b * PRED + (t - LABEL)) * MMK + m];
}

__global__ void __launch_bounds__(512) k_embed(
    const float* __restrict__ x, const float* __restrict__ mark,
    const float* __restrict__ Wc, const float* __restrict__ Wm,
    float* __restrict__ out, int L) {
    __shared__ float xs[10 * CC];
    __shared__ float ms[8 * MMK];
    int blk = blockIdx.x;
    int nch = L >> 3;
    int b = blk / nch, t0 = (blk % nch) << 3;
    int tid = threadIdx.x;
    if (tid < 10 * CC) {
        int r = tid / CC, c = tid % CC;
        int tt = (t0 - 1 + r + L) % L;
        xs[tid] = x[(b * L + tt) * CC + c];
    } else if (tid < 10 * CC + 8 * MMK) {
        int q = tid - 10 * CC;
        int r = q / MMK, m = q % MMK;
        ms[q] = mark[(b * L + t0 + r) * MMK + m];
    }
    __syncthreads();
    int o = tid;
    float wc[3 * CC], wm[MMK];
#pragma unroll
    for (int i = 0; i < 3 * CC; i++) wc[i] = Wc[i * DM + o];
#pragma unroll
    for (int m = 0; m < MMK; m++) wm[m] = Wm[m * DM + o];
#pragma unroll
    for (int r = 0; r < 8; r++) {
        float s = 0.f;
#pragma unroll
        for (int w = 0; w < 3; w++)
#pragma unroll
            for (int c = 0; c < CC; c++)
                s += xs[(r + w) * CC + c] * wc[w * CC + c];
#pragma unroll
        for (int m = 0; m < MMK; m++) s += ms[r * MMK + m] * wm[m];
        out[((size_t)(b * L + t0 + r)) * DM + o] = s;
    }
}

__global__ void k_zero(float* __restrict__ p, int n) {
    int i = blockIdx.x * blockDim.x + threadIdx.x;
    int n4 = n >> 2;
    if (i < n4) {
        ((float4*)p)[i] = make_float4(0.f, 0.f, 0.f, 0.f);
    } else {
        int r = n4 * 4 + (i - n4);
        if (r < n) p[r] = 0.f;
    }
}

__global__ void k_zero_pad(float* __restrict__ p, int r0, int rpb) {
    int idx = blockIdx.x * blockDim.x + threadIdx.x;
    int nPadRows = rpb - r0;
    if (idx >= BATCH * nPadRows * (DM / 4)) return;
    int d4 = idx % (DM / 4);
    int rest = idx / (DM / 4);
    int r = rest % nPadRows;
    int b = rest / nPadRows;
    *(float4*)&p[((size_t)(b * rpb + r0 + r)) * DM + d4 * 4] =
        make_float4(0.f, 0.f, 0.f, 0.f);
}

__global__ void k_decomp_sw(const float* __restrict__ S, float* __restrict__ seas,
                            float* __restrict__ trend, int L, int mode) {
    int idx = blockIdx.x * blockDim.x + threadIdx.x;
    if (idx >= BATCH * DM * NCH) return;
    int d = idx % DM;
    int rest = idx / DM;
    int ch = rest % NCH;
    int b = rest / NCH;
    int CL = (L + NCH - 1) / NCH;
    int t0 = ch * CL;
    int t1 = t0 + CL < L ? t0 + CL : L;
    if (t0 >= L) return;
    const float* base = S + (size_t)b * L * DM + d;
    float s = 0.f;
#pragma unroll
    for (int u = -KHALF; u <= KHALF; u++) {
        int tt = t0 + u; tt = tt < 0 ? 0 : (tt >= L ? L - 1 : tt);
        s += base[(size_t)tt * DM];
    }
    for (int t = t0; t < t1; t++) {
        float m = s * (1.f / KSZ);
        size_t o = ((size_t)(b * L + t)) * DM + d;
        seas[o] = base[(size_t)t * DM] - m;
        if (mode == 1) trend[o] = m;
        else if (mode == 2) trend[o] += m;
        int rm = t - KHALF; rm = rm < 0 ? 0 : rm;
        int ad = t + KHALF + 1; ad = ad >= L ? L - 1 : ad;
        s += base[(size_t)ad * DM] - base[(size_t)rm * DM];
    }
}

__global__ void __launch_bounds__(256) k_topk(const float* __restrict__ mc,
                                              float* __restrict__ w, int* __restrict__ dly,
                                              int L, int K) {
    __shared__ float vals[LDEC];
    __shared__ float rv[256];
    __shared__ int ri[256];
    __shared__ float selv[32];
    __shared__ int seli[32];
    int b = blockIdx.x, tid = threadIdx.x;
    for (int j = tid; j < L; j += 256) vals[j] = mc[b * L + j];
    __syncthreads();
    for (int it = 0; it < K; it++) {
        float best = -1e30f; int bi = 0;
        for (int j = tid; j < L; j += 256) {
            float v = vals[j];
            if (v > best) { best = v; bi = j; }
        }
        rv[tid] = best; ri[tid] = bi;
        __syncthreads();
        for (int s = 128; s > 0; s >>= 1) {
            if (tid < s) {
                if (rv[tid + s] > rv[tid] ||
                    (rv[tid + s] == rv[tid] && ri[tid + s] < ri[tid])) {
                    rv[tid] = rv[tid + s]; ri[tid] = ri[tid + s];
                }
            }
            __syncthreads();
        }
        if (tid == 0) { selv[it] = rv[0]; seli[it] = ri[0]; vals[ri[0]] = -1e30f; }
        __syncthreads();
    }
    if (tid == 0) {
        float mx = selv[0], ssum = 0.f;
        for (int i = 0; i < K; i++) { float e = expf(selv[i] - mx); selv[i] = e; ssum += e; }
        for (int i = 0; i < K; i++) { w[b * 32 + i] = selv[i] / ssum; dly[b * 32 + i] = seli[i]; }
    }
}

__global__ void __launch_bounds__(128) k_agg(
    const float* __restrict__ v, const float* __restrict__ w,
    const int* __restrict__ dly, float* __restrict__ out, int L, int K) {
    __shared__ float ws[32];
    __shared__ int ds[32];
    int blk = blockIdx.x;
    int b = blk / L, t = blk % L;
    int d4 = threadIdx.x;
    if (d4 < K) { ws[d4] = w[b * 32 + d4]; ds[d4] = dly[b * 32 + d4]; }
    __syncthreads();
    float4 s = make_float4(0.f, 0.f, 0.f, 0.f);
    for (int i = 0; i < K; i++) {
        int tt = t + ds[i]; if (tt >= L) tt -= L;
        float4 vv = *(const float4*)&v[((size_t)(b * L + tt)) * DM + d4 * 4];
        float wi = ws[i];
        s.x += wi * vv.x; s.y += wi * vv.y; s.z += wi * vv.z; s.w += wi * vv.w;
    }
    *(float4*)&out[((size_t)(b * L + t)) * DM + d4 * 4] = s;
}

__global__ void __launch_bounds__(128) k_ln(const float* __restrict__ X,
                                            const float* __restrict__ g,
                                            const float* __restrict__ be,
                                            float* __restrict__ Y) {
    __shared__ float red[4];
    int row = blockIdx.x, tid = threadIdx.x;
    int lane = tid & 31, warp = tid >> 5;
    float4 xv = *(const float4*)&X[(size_t)row * DM + tid * 4];

    float s = xv.x + xv.y + xv.z + xv.w;
#pragma unroll
    for (int o = 16; o > 0; o >>= 1) s += __shfl_down_sync(0xffffffffu, s, o);
    if (lane == 0) red[warp] = s;
    __syncthreads();
    float mu = (red[0] + red[1] + red[2] + red[3]) * (1.f / DM);
    __syncthreads();

    float4 dv = make_float4(xv.x - mu, xv.y - mu, xv.z - mu, xv.w - mu);
    float v = dv.x * dv.x + dv.y * dv.y + dv.z * dv.z + dv.w * dv.w;
#pragma unroll
    for (int o = 16; o > 0; o >>= 1) v += __shfl_down_sync(0xffffffffu, v, o);
    if (lane == 0) red[warp] = v;
    __syncthreads();
    float inv = rsqrtf((red[0] + red[1] + red[2] + red[3]) * (1.f / DM) + 1e-5f);

    float4 gv = *(const float4*)&g[tid * 4];
    float4 bv = *(const float4*)&be[tid * 4];
    float4 yv = make_float4(dv.x * inv * gv.x + bv.x, dv.y * inv * gv.y + bv.y,
                            dv.z * inv * gv.z + bv.z, dv.w * inv * gv.w + bv.w);
    *(float4*)&Y[(size_t)row * DM + tid * 4] = yv;
}

__global__ void __launch_bounds__(128) k_colsum(const float* __restrict__ Y,
                                                float* __restrict__ cm, int L) {
    int b = blockIdx.x, chunk = blockIdx.y, nch = gridDim.y;
    int d4 = threadIdx.x;
    float4 s = make_float4(0.f, 0.f, 0.f, 0.f);
    for (int t = chunk; t < L; t += nch) {
        float4 y = *(const float4*)&Y[((size_t)(b * L + t)) * DM + d4 * 4];
        s.x += y.x; s.y += y.y; s.z += y.z; s.w += y.w;
    }
    atomicAdd(&cm[b * DM + d4 * 4 + 0], s.x);
    atomicAdd(&cm[b * DM + d4 * 4 + 1], s.y);
    atomicAdd(&cm[b * DM + d4 * 4 + 2], s.z);
    atomicAdd(&cm[b * DM + d4 * 4 + 3], s.w);
}

__global__ void k_subcm(float* __restrict__ Y, const float* __restrict__ cm, int L) {
    size_t i4 = (size_t)blockIdx.x * blockDim.x + threadIdx.x;
    size_t total4 = (size_t)BATCH * L * DM / 4;
    if (i4 >= total4) return;
    int d4 = (int)(i4 % (DM / 4));
    int b = (int)(i4 / ((size_t)L * (DM / 4)));
    float4 y = *(float4*)&Y[i4 * 4];
    float4 c = *(const float4*)&cm[b * DM + d4 * 4];
    float invL = 1.f / (float)L;
    y.x -= c.x * invL; y.y -= c.y * invL; y.z -= c.z * invL; y.w -= c.w * invL;
    *(float4*)&Y[i4 * 4] = y;
}

__global__ void __launch_bounds__(224) k_final(const float* __restrict__ xh,
                                               const float* __restrict__ tsum,
                                               const float* __restrict__ tdec,
                                               const float* __restrict__ Wtr,
                                               const float* __restrict__ Wp,
                                               const float* __restrict__ bp,
                                               float* __restrict__ out) {
    __shared__ float xs[DM];
    __shared__ float ts[3][DM];
    int blk = blockIdx.x;
    int b = blk / PRED, to = blk % PRED;
    int t = to + LABEL;
    int tid = threadIdx.x;
    for (int d = tid; d < DM; d += 224) xs[d] = xh[((size_t)(b * LDEC + t)) * DM + d];
    for (int w = 0; w < 3; w++) {
        int tt = (t - 1 + w + LDEC) % LDEC;
        for (int d = tid; d < DM; d += 224) ts[w][d] = tsum[((size_t)(b * LDEC + tt)) * DM + d];
    }
    __syncthreads();
    int c = tid >> 5, lane = tid & 31;
    float s = 0.f;
    for (int d = lane; d < DM; d += 32) {
        s += xs[d] * Wp[d * CC + c];
        s += ts[0][d] * Wtr[(0 * DM + d) * CC + c];
        s += ts[1][d] * Wtr[(1 * DM + d) * CC + c];
        s += ts[2][d] * Wtr[(2 * DM + d) * CC + c];
    }
    for (int o = 16; o > 0; o >>= 1) s += __shfl_down_sync(0xffffffffu, s, o);
    if (lane == 0)
        out[(b * PRED + to) * CC + c] = s + bp[c] + tdec[(b * LDEC + t) * CC + c];
}

// ---------------- host orchestration ----------------
extern "C" void kernel_launch(void* const* d_in, const int* in_sizes, int n_in,
                              void* d_out, int out_size) {
    const float* x_enc      = (const float*)d_in[0];
    const float* x_mark_enc = (const float*)d_in[1];
    const float* x_mark_dec = (const float*)d_in[3];
    const float* W_enc_emb  = (const float*)d_in[4];
    const float* W_mark_enc = (const float*)d_in[5];
    const float* W_dec_emb  = (const float*)d_in[6];
    const float* W_mark_dec = (const float*)d_in[7];
    const float* eW_attn    = (const float*)d_in[8];
    const float* eb_attn    = (const float*)d_in[9];
    const float* eW1        = (const float*)d_in[10];
    const float* eW2        = (const float*)d_in[11];
    const float* eg         = (const float*)d_in[12];
    const float* ebeta      = (const float*)d_in[13];
    const float* sW         = (const float*)d_in[14];
    const float* sb         = (const float*)d_in[15];
    const float* cW         = (const float*)d_in[16];
    const float* cb         = (const float*)d_in[17];
    const float* dW1        = (const float*)d_in[18];
    const float* dW2        = (const float*)d_in[19];
    const float* W_trend    = (const float*)d_in[20];
    const float* dg         = (const float*)d_in[21];
    const float* dbeta      = (const float*)d_in[22];
    const float* Wproj      = (const float*)d_in[23];
    const float* bproj      = (const float*)d_in[24];
    float* out = (float*)d_out;

    void* p;
    float *x, *sum, *q, *k, *v, *agg, *enc, *ffn, *tsum, *mc, *wts, *cm, *m7, *s7, *t7, *sdec, *tdec, *mdec;
    int* dly;
    cudaGetSymbolAddress(&p, g_x);    x    = (float*)p;
    cudaGetSymbolAddress(&p, g_sum);  sum  = (float*)p;
    cudaGetSymbolAddress(&p, g_q);    q    = (float*)p;
    cudaGetSymbolAddress(&p, g_k);    k    = (float*)p;
    cudaGetSymbolAddress(&p, g_v);    v    = (float*)p;
    cudaGetSymbolAddress(&p, g_agg);  agg  = (float*)p;
    cudaGetSymbolAddress(&p, g_enc);  enc  = (float*)p;
    cudaGetSymbolAddress(&p, g_ffn);  ffn  = (float*)p;
    cudaGetSymbolAddress(&p, g_tsum); tsum = (float*)p;
    cudaGetSymbolAddress(&p, g_mc);   mc   = (float*)p;
    cudaGetSymbolAddress(&p, g_wts);  wts  = (float*)p;
    cudaGetSymbolAddress(&p, g_dly);  dly  = (int*)p;
    cudaGetSymbolAddress(&p, g_cm);   cm   = (float*)p;
    cudaGetSymbolAddress(&p, g_m7);   m7   = (float*)p;
    cudaGetSymbolAddress(&p, g_s7);   s7   = (float*)p;
    cudaGetSymbolAddress(&p, g_t7);   t7   = (float*)p;
    cudaGetSymbolAddress(&p, g_sdec); sdec = (float*)p;
    cudaGetSymbolAddress(&p, g_tdec); tdec = (float*)p;
    cudaGetSymbolAddress(&p, g_mdec); mdec = (float*)p;

    const int rowsE = BATCH * LE;     // 16384
    const int rowsD = BATCH * LDEC;   // 18944
    const int KE = (int)(3.0 * log(512.0));  // 18
    const int KD = (int)(3.0 * log(592.0));  // 19

    auto GT = [](int M, int N) { return dim3((unsigned)(N / 128), (unsigned)(M / 128), 1); };

    // ---- series_decomp of x_enc + decoder inits ----
    k_mean7<<<(BATCH * CC * 32 + 255) / 256, 256>>>(x_enc, m7);
    {
        int n = BATCH * LE * CC;
        k_decomp7<<<(n + 255) / 256, 256>>>(x_enc, s7, t7);
    }
    {
        int n = BATCH * LDEC * CC;
        k_build_dec<<<(n + 255) / 256, 256>>>(s7, t7, m7, sdec, tdec);
        int nm = BATCH * LDEC * MMK;
        k_build_mark<<<(nm + 255) / 256, 256>>>(x_mark_enc, x_mark_dec, mdec);
    }

    // ---- attention helper: writes outBuf = resBuf + attn_out ----
    auto attn = [&](const float* qin, const float* kin, const float* vin,
                    int rowsQ, int rowsKV, int L, int Lk, int Kk,
                    const float* W, const float* bb, bool kvPad,
                    const float* resBuf, float* outBuf) {
        mma_gemm<<<GT(rowsQ, DM), 256>>>(qin, W, bb, nullptr, q, rowsQ, DM, DM, 1, 1, 0);
        if (kvPad) {
            // only V's pad rows are ever read (k_agg); K pad rows guarded by Lk
            int nPad4 = BATCH * (LDEC - LE) * (DM / 4);
            k_zero_pad<<<(nPad4 + 255) / 256, 256>>>(v, LE, LDEC);
            mma_gemm<<<GT(rowsKV, DM), 256>>>(kin, W + DM * DM, bb + DM, nullptr, k, rowsKV, DM, DM, LE, LDEC, 0);
            mma_gemm<<<GT(rowsKV, DM), 256>>>(vin, W + 2 * DM * DM, bb + 2 * DM, nullptr, v, rowsKV, DM, DM, LE, LDEC, 0);
        } else {
            mma_gemm<<<GT(rowsKV, DM), 256>>>(kin, W + DM * DM, bb + DM, nullptr, k, rowsKV, DM, DM, 1, 1, 0);
            mma_gemm<<<GT(rowsKV, DM), 256>>>(vin, W + 2 * DM * DM, bb + 2 * DM, nullptr, v, rowsKV, DM, DM, 1, 1, 0);
        }
        int n = BATCH * L;
        k_zero<<<(n + 255) / 256, 256>>>(mc, n);
        mma_nt_fold<<<dim3((unsigned)((Lk + 127) / 128), (unsigned)((L + 127) / 128), BATCH), 256>>>(q, k, mc, L, Lk, DM);
        k_topk<<<BATCH, 256>>>(mc, wts, dly, L, Kk);
        k_agg<<<BATCH * L, 128>>>(v, wts, dly, agg, L, Kk);
        mma_gemm<<<GT(rowsQ, DM), 256>>>(agg, W + 3 * DM * DM, bb + 3 * DM, resBuf, outBuf, rowsQ, DM, DM, 1, 1, 0);
    };

    const int nSW = BATCH * DM * NCH;

    // ================= encoder =================
    k_embed<<<BATCH * (LE / 8), 512>>>(x_enc, x_mark_enc, W_enc_emb, W_mark_enc, x, LE);

    for (int l = 0; l < 2; l++) {
        const float* W  = eW_attn + (size_t)l * 4 * DM * DM;
        const float* bb = eb_attn + (size_t)l * 4 * DM;
        attn(x, x, x, rowsE, rowsE, LE, LE, KE, W, bb, false, x, sum);   // sum = x + attn(x)
        k_decomp_sw<<<(nSW + 255) / 256, 256>>>(sum, x, tsum, LE, 0);
        mma_gemm<<<GT(rowsE, DFF), 256>>>(x, eW1 + (size_t)l * DM * DFF, nullptr, nullptr, ffn, rowsE, DFF, DM, 1, 1, 1);
        mma_gemm<<<GT(rowsE, DM), 256>>>(ffn, eW2 + (size_t)l * DFF * DM, nullptr, x, sum, rowsE, DM, DFF, 1, 1, 0);
        k_decomp_sw<<<(nSW + 255) / 256, 256>>>(sum, x, tsum, LE, 0);
    }
    // enc_out = my_layernorm(x, eg, ebeta)
    k_ln<<<rowsE, 128>>>(x, eg, ebeta, enc);
    {
        int n = BATCH * DM;
        k_zero<<<(n + 255) / 256, 256>>>(cm, n);
        k_colsum<<<dim3(BATCH, 8), 128>>>(enc, cm, LE);
        int n4 = rowsE * DM / 4;
        k_subcm<<<(n4 + 255) / 256, 256>>>(enc, cm, LE);
    }

    // ================= decoder =================
    k_embed<<<BATCH * (LDEC / 8), 512>>>(sdec, mdec, W_dec_emb, W_mark_dec, x, LDEC);

    // self attention
    attn(x, x, x, rowsD, rowsD, LDEC, LDEC, KD, sW, sb, false, x, sum);
    k_decomp_sw<<<(nSW + 255) / 256, 256>>>(sum, x, tsum, LDEC, 1);   // write t1

    // cross attention (K/V from encoder output, zero-padded 512->592)
    attn(x, enc, enc, rowsD, rowsE, LDEC, LE, KD, cW, cb, true, x, sum);
    k_decomp_sw<<<(nSW + 255) / 256, 256>>>(sum, x, tsum, LDEC, 2);   // += t2

    // FFN
    mma_gemm<<<GT(rowsD, DFF), 256>>>(x, dW1, nullptr, nullptr, ffn, rowsD, DFF, DM, 1, 1, 1);
    mma_gemm<<<GT(rowsD, DM), 256>>>(ffn, dW2, nullptr, x, sum, rowsD, DM, DFF, 1, 1, 0);
    k_decomp_sw<<<(nSW + 255) / 256, 256>>>(sum, x, tsum, LDEC, 2);   // += t3

    // my_layernorm(x, dg, dbeta) -> sum (reused as xh buffer)
    k_ln<<<rowsD, 128>>>(x, dg, dbeta, sum);
    {
        int n = BATCH * DM;
        k_zero<<<(n + 255) / 256, 256>>>(cm, n);
        k_colsum<<<dim3(BATCH, 8), 128>>>(sum, cm, LDEC);
        int n4 = rowsD * DM / 4;
        k_subcm<<<(n4 + 255) / 256, 256>>>(sum, cm, LDEC);
    }

    // final: seasonal projection + trend conv + slice
    k_final<<<BATCH * PRED, 224>>>(sum, tsum, tdec, W_trend, Wproj, bproj, out);
}